// round 12
// baseline (speedup 1.0000x reference)
#include <cuda_runtime.h>
#include <math.h>

namespace {
constexpr int    Bn = 32, Cn = 32, Ln = 16384, WIN = 64, HOP = 32;
constexpr int    NF = 511, ND = 33;
constexpr double PEN = 5.0;
constexpr int    MAXSEG = 520, MAXTOK = 4608, ANCH = 16;
constexpr double PI_D = 3.14159265358979323846264338327950288;
constexpr int    SEGBUF = 1024;
// k_pelt dynamic smem layout (doubles): cs 16896 | s2 512 | Fc 512 | vals 512 | recip 512
constexpr int    PELT_DBL  = 16896 + 512 + 512 + 512 + 512;
constexpr size_t PELT_SMEM = PELT_DBL * 8 + (512 + 514) * 2 + 16;
}

// ------------------------------- scratch ----------------------------------
__device__ float  g_x[Bn][Cn][Ln];
__device__ float  g_sig[Bn][Ln];
__device__ double g_feats[Bn][NF][ND];
__device__ double g_cs [Bn][NF + 1][ND];
__device__ double g_cs2[Bn][NF + 1][ND];
__device__ double g_s2 [Bn][NF + 1];
__device__ int    g_nseg[Bn];
__device__ int    g_seg_s[Bn][MAXSEG];
__device__ int    g_seg_e[Bn][MAXSEG];
__device__ int    g_seg_off[Bn][MAXSEG];
__device__ double g_spec[Bn][Ln / 2 + 8];
__device__ double g_dp[Bn][MAXSEG];
__device__ double g_bwv[Bn][MAXSEG];
__device__ int    g_pl[Bn][MAXSEG];
__device__ int    g_ntok[Bn];
__device__ int    g_tok_s[Bn][MAXTOK];
__device__ int    g_tok_e[Bn][MAXTOK];
__device__ int    g_tok_seg[Bn][MAXTOK];

// precomputed constants
__device__ float2 c_tw_re[WIN], c_tw_im[WIN], c_win[WIN];
__device__ float2 c_c32[17];
__device__ float2 c_lnc[11];
__device__ float2 c_ln2;
__device__ float2 c_eps;
__device__ double c_recip[NF + 1];

// ---------------------------- double-single ops ----------------------------
struct DS { float hi, lo; };
__device__ __forceinline__ DS two_sum(float a, float b) {
    float s = a + b, bb = s - a;
    float e = (a - (s - bb)) + (b - bb);
    return {s, e};
}
__device__ __forceinline__ DS quick2(float a, float b) {
    float s = a + b;
    return {s, b - (s - a)};
}
__device__ __forceinline__ DS ds_add(DS a, DS b) {
    DS s = two_sum(a.hi, b.hi);
    return quick2(s.hi, s.lo + a.lo + b.lo);
}
__device__ __forceinline__ DS ds_mul(DS a, DS b) {
    float p = a.hi * b.hi;
    float e = fmaf(a.hi, b.hi, -p);
    e = fmaf(a.hi, b.lo, e);
    e = fmaf(a.lo, b.hi, e);
    return quick2(p, e);
}
__device__ __forceinline__ DS ds_neg(DS a) { return {-a.hi, -a.lo}; }
__device__ __forceinline__ DS ds_from_d(double v) {
    float hi = (float)v;
    return {hi, (float)(v - (double)hi)};
}

// DS natural log; v > 0 well inside float range. abs err ~1e-13.
__device__ DS ds_log(DS v) {
    int e;
    float mh = frexpf(v.hi, &e);
    if (mh < 0.7071067811865476f) e -= 1;
    float sc = ldexpf(1.0f, -e);
    DS m = {v.hi * sc, v.lo * sc};
    DS num = ds_add(m, {-1.0f, 0.0f});
    DS den = ds_add(m, { 1.0f, 0.0f});
    float r = 1.0f / den.hi;
    float q1 = num.hi * r;
    DS t  = ds_add(num, ds_neg(ds_mul(den, {q1, 0.f})));
    float q2 = t.hi * r;
    DS t2 = ds_add(t,  ds_neg(ds_mul(den, {q2, 0.f})));
    float q3 = t2.hi * r;
    DS z = ds_add(ds_add({q1, 0.f}, {q2, 0.f}), {q3, 0.f});
    DS w = ds_mul(z, z);
    DS p = {c_lnc[10].x, c_lnc[10].y};
    #pragma unroll
    for (int k = 9; k >= 0; --k)
        p = ds_add(ds_mul(p, w), {c_lnc[k].x, c_lnc[k].y});
    DS lnm = ds_mul(ds_mul({2.0f, 0.f}, z), p);
    return ds_add(ds_mul({(float)e, 0.f}, {c_ln2.x, c_ln2.y}), lnm);
}

// numpy pairwise sum (float32), exact replication
__device__ float np_pairwise_sum(const float* a, int n) {
    if (n < 8) {
        float r = 0.0f;
        for (int i = 0; i < n; ++i) r += a[i];
        return r;
    } else if (n <= 128) {
        float r[8];
        #pragma unroll
        for (int j = 0; j < 8; ++j) r[j] = a[j];
        int i = 8;
        for (; i < n - (n % 8); i += 8) {
            #pragma unroll
            for (int j = 0; j < 8; ++j) r[j] += a[i + j];
        }
        float res = ((r[0] + r[1]) + (r[2] + r[3])) + ((r[4] + r[5]) + (r[6] + r[7]));
        for (; i < n; ++i) res += a[i];
        return res;
    } else {
        int n2 = n / 2;
        n2 -= n2 % 8;
        return np_pairwise_sum(a, n2) + np_pairwise_sum(a + n2, n - n2);
    }
}

// ------------------------------ 0) init ------------------------------------
__global__ void k_init() {
    int i = threadIdx.x;
    if (i < WIN) {
        double ang = -2.0 * PI_D * (double)i / 64.0;
        double sn, co;
        sincos(ang, &sn, &co);
        DS a = ds_from_d(co), b = ds_from_d(sn);
        c_tw_re[i] = make_float2(a.hi, a.lo);
        c_tw_im[i] = make_float2(b.hi, b.lo);
        DS wd = ds_from_d(0.5 - 0.5 * cos(2.0 * PI_D * (double)i / 63.0));
        c_win[i] = make_float2(wd.hi, wd.lo);
    }
    if (i <= 16) {
        DS c = ds_from_d(2.0 * cos(2.0 * PI_D * (double)i / 32.0));
        c_c32[i] = make_float2(c.hi, c.lo);
    }
    if (i <= 10) {
        DS c = ds_from_d(1.0 / (double)(2 * i + 1));
        c_lnc[i] = make_float2(c.hi, c.lo);
    }
    if (i == 0) {
        DS l2 = ds_from_d(0.69314718055994530941723212145818);
        c_ln2 = make_float2(l2.hi, l2.lo);
        DS ep = ds_from_d(1e-8);
        c_eps = make_float2(ep.hi, ep.lo);
    }
    if (i <= NF) c_recip[i] = i ? 1.0 / (double)i : 0.0;
}

// -------- 1) stage x -> g_x (HBM) + channel mean (float4 streaming) ---------
__global__ void k_sig(const float* __restrict__ x) {
    int t4 = blockIdx.x * blockDim.x + threadIdx.x;
    int b = blockIdx.y;
    if (t4 >= Ln / 4) return;
    const float4* p = (const float4*)(x + (size_t)b * Cn * Ln) + t4;
    float4 s = make_float4(0.f, 0.f, 0.f, 0.f);
    #pragma unroll
    for (int c = 0; c < Cn; ++c) {
        float4 v = p[(size_t)c * (Ln / 4)];
        ((float4*)g_x[b][c])[t4] = v;
        s.x += v.x; s.y += v.y; s.z += v.z; s.w += v.w;
    }
    s.x *= 0.03125f; s.y *= 0.03125f; s.z *= 0.03125f; s.w *= 0.03125f;
    ((float4*)g_sig[b])[t4] = s;
}

// ------------- 2) spectrogram features (DS fp32 DFT + DS log) --------------
__global__ void k_feats() {
    __shared__ float2 sv[WIN];
    __shared__ float2 twr[WIN], twi[WIN];
    __shared__ float  fr[WIN];
    __shared__ float  smean;
    int b = blockIdx.y, f = blockIdx.x, i = threadIdx.x;

    twr[i] = c_tw_re[i]; twi[i] = c_tw_im[i];
    fr[i] = g_sig[b][f * HOP + i];
    __syncthreads();

    if (i == 0) {
        float r[8];
        #pragma unroll
        for (int j = 0; j < 8; ++j) r[j] = fr[j];
        for (int o = 8; o < 64; o += 8) {
            #pragma unroll
            for (int j = 0; j < 8; ++j) r[j] += fr[o + j];
        }
        float s = ((r[0] + r[1]) + (r[2] + r[3])) + ((r[4] + r[5]) + (r[6] + r[7]));
        smean = s / 64.0f;
    }
    __syncthreads();

    {
        float d = fr[i] - smean;
        float2 w = c_win[i];
        float p = d * w.x;
        float e = fmaf(d, w.x, -p);
        e = fmaf(d, w.y, e);
        DS r = quick2(p, e);
        sv[i] = make_float2(r.hi, r.lo);
    }
    __syncthreads();

    if (i < ND) {
        DS re = {0.f, 0.f}, im = {0.f, 0.f};
        #pragma unroll 4
        for (int t = 0; t < WIN; ++t) {
            int m = (i * t) & 63;
            DS v  = {sv[t].x, sv[t].y};
            DS cr = {twr[m].x, twr[m].y};
            DS ci = {twi[m].x, twi[m].y};
            re = ds_add(re, ds_mul(v, cr));
            im = ds_add(im, ds_mul(v, ci));
        }
        DS p2 = ds_add(ds_mul(re, re), ds_mul(im, im));
        p2 = ds_add(p2, {c_eps.x, c_eps.y});
        DS lg = ds_log(p2);
        g_feats[b][f][i] = (double)lg.hi + (double)lg.lo;
    }
}

// -------- 3a) prefix sums: warp-per-(d,b) Kogge-Stone scan with carry -------
__global__ void k_prefix() {
    int d = blockIdx.x, b = blockIdx.y, lane = threadIdx.x;
    double carry = 0.0, carry2 = 0.0;
    if (lane == 0) { g_cs[b][0][d] = 0.0; g_cs2[b][0][d] = 0.0; }
    for (int base = 0; base < NF; base += 32) {
        int t = base + lane;
        double v  = (t < NF) ? g_feats[b][t][d] : 0.0;
        double v2 = v * v;
        #pragma unroll
        for (int o = 1; o < 32; o <<= 1) {
            double n1 = __shfl_up_sync(0xffffffffu, v,  o);
            double n2 = __shfl_up_sync(0xffffffffu, v2, o);
            if (lane >= o) { v += n1; v2 += n2; }
        }
        v += carry; v2 += carry2;
        if (t < NF) {
            g_cs[b][t + 1][d]  = v;
            g_cs2[b][t + 1][d] = v2;
        }
        carry  = __shfl_sync(0xffffffffu, v, 31);
        carry2 = __shfl_sync(0xffffffffu, v2, 31);
    }
}

// -------- 3b) S2 totals: sum over d of cs2 ----------------------------------
__global__ void k_s2() {
    int b = blockIdx.x, t = threadIdx.x;
    double s = 0.0;
    #pragma unroll
    for (int dd = 0; dd < ND; ++dd) s += g_cs2[b][t][dd];
    g_s2[b][t] = s;
}

// ------ 4) PELT DP: warp/batch, register-resident fast path (ncand<=4) ------
__global__ void k_pelt() {
    extern __shared__ double dyn[];
    double* s_cs    = dyn;                 // 16896 = 512*33
    double* s_s2    = dyn + 16896;         // 512
    double* s_Fc    = dyn + 17408;         // 512
    double* s_vals  = dyn + 17920;         // 512
    double* s_recip = dyn + 18432;         // 512
    short*  s_prev  = (short*)(dyn + 18944);        // 512 shorts
    short*  s_cands = s_prev + 512;                 // 514 shorts

    int b = blockIdx.x, tid = threadIdx.x;

    const double* gc = (const double*)g_cs[b];
    for (int i = tid; i < 16896; i += 256) s_cs[i] = gc[i];
    for (int i = tid; i < 512;   i += 256) {
        s_s2[i]    = g_s2[b][i];
        s_recip[i] = c_recip[i];
    }
    __syncthreads();
    if (tid >= 32) return;

    int lane = tid;
    int cg = lane >> 3;   // candidate group (0..3)
    int dl = lane & 7;    // dim lane (0..7)

    // uniform candidate registers (slots 0..3)
    int    c0 = 0, c1 = 0, c2 = 0, c3 = 0;
    double F0 = -PEN, F1 = 0, F2 = 0, F3 = 0;
    double S20 = 0.0, S21 = 0, S22 = 0, S23 = 0;
    int ncand = 1;
    bool fast = true;

    // lane-distributed: row of this group's candidate (dims dl+8q)
    double pcd[5];
    #pragma unroll
    for (int q = 0; q < 5; ++q) {
        int d = dl + q * 8;
        pcd[q] = (d < ND) ? s_cs[0 * 33 + d] : 0.0;   // cs[0] row = zeros
    }
    if (lane == 0) { s_Fc[0] = -PEN; s_cands[0] = 0; }
    __syncwarp();

    for (int t = 1; t <= NF; ++t) {
        const double* ct = s_cs + t * 33;
        double U = s_s2[t];
        double ctd[5];
        #pragma unroll
        for (int q = 0; q < 5; ++q) {
            int d = dl + q * 8;
            ctd[q] = (d < ND) ? ct[d] : 0.0;
        }

        if (fast) {
            // uniform per-slot recip (loaded early, off chain)
            double r0 = s_recip[t - c0];
            double r1 = (ncand > 1) ? s_recip[t - c1] : 0.0;
            double r2 = (ncand > 2) ? s_recip[t - c2] : 0.0;
            double r3 = (ncand > 3) ? s_recip[t - c3] : 0.0;
            double p0 = U - S20, p1 = U - S21, p2 = U - S22, p3 = U - S23;

            // lane-group cost accumulation (dual accumulators)
            bool act = (cg < ncand);
            double a0 = 0.0, a1 = 0.0;
            if (act) {
                double s0q = ctd[0] - pcd[0]; a0 = fma(s0q, s0q, a0);
                double s1q = ctd[1] - pcd[1]; a1 = fma(s1q, s1q, a1);
                double s2q = ctd[2] - pcd[2]; a0 = fma(s2q, s2q, a0);
                double s3q = ctd[3] - pcd[3]; a1 = fma(s3q, s3q, a1);
                double s4q = ctd[4] - pcd[4]; a0 = fma(s4q, s4q, a0);
            }
            double acc = a0 + a1;
            acc += __shfl_down_sync(0xffffffffu, acc, 4);
            acc += __shfl_down_sync(0xffffffffu, acc, 2);
            acc += __shfl_down_sync(0xffffffffu, acc, 1);
            double acc0 = __shfl_sync(0xffffffffu, acc, 0);
            double acc1 = __shfl_sync(0xffffffffu, acc, 8);
            double acc2 = __shfl_sync(0xffffffffu, acc, 16);
            double acc3 = __shfl_sync(0xffffffffu, acc, 24);

            // uniform vals (same expression shape as general path)
            double v0 = (F0 + (p0 - acc0 * r0)) + PEN;
            double v1 = (ncand > 1) ? (F1 + (p1 - acc1 * r1)) + PEN : 1e300;
            double v2 = (ncand > 2) ? (F2 + (p2 - acc2 * r2)) + PEN : 1e300;
            double v3 = (ncand > 3) ? (F3 + (p3 - acc3 * r3)) + PEN : 1e300;

            // argmin, first-index tiebreak
            double bv = v0; int bj = 0;
            if (v1 < bv) { bv = v1; bj = 1; }
            if (v2 < bv) { bv = v2; bj = 2; }
            if (v3 < bv) { bv = v3; bj = 3; }
            int prevc = (bj == 0) ? c0 : (bj == 1) ? c1 : (bj == 2) ? c2 : c3;
            if (lane == 0) { s_Fc[t] = bv; s_prev[t] = (short)prevc; }

            // prune (uniform)
            double thr = bv + PEN;
            bool k0 = (v0 <= thr);
            bool k1 = (ncand > 1) && (v1 <= thr);
            bool k2 = (ncand > 2) && (v2 <= thr);
            bool k3 = (ncand > 3) && (v3 <= thr);

            int srcm[4] = {0, 0, 0, 0};
            int newn = 0;
            #pragma unroll
            for (int j = 0; j < 4; ++j) {
                bool kj = (j == 0) ? k0 : (j == 1) ? k1 : (j == 2) ? k2 : k3;
                if (kj) {
                    if (newn == 0) srcm[0] = j;
                    else if (newn == 1) srcm[1] = j;
                    else if (newn == 2) srcm[2] = j;
                    else srcm[3] = j;
                    ++newn;
                }
            }

            // survivor values (uniform selects)
            #define SELC(s_) ((s_)==0?c0:(s_)==1?c1:(s_)==2?c2:c3)
            #define SELF(s_) ((s_)==0?F0:(s_)==1?F1:(s_)==2?F2:F3)
            #define SELS(s_) ((s_)==0?S20:(s_)==1?S21:(s_)==2?S22:S23)
            int    nc0 = SELC(srcm[0]), nc1 = SELC(srcm[1]), nc2 = SELC(srcm[2]), nc3 = SELC(srcm[3]);
            double nF0 = SELF(srcm[0]), nF1 = SELF(srcm[1]), nF2 = SELF(srcm[2]), nF3 = SELF(srcm[3]);
            double nS0 = SELS(srcm[0]), nS1 = SELS(srcm[1]), nS2 = SELS(srcm[2]), nS3 = SELS(srcm[3]);
            #undef SELC
            #undef SELF
            #undef SELS

            // move pcd rows between lane groups (register shuffle)
            int msrc = (cg == 0) ? srcm[0] : (cg == 1) ? srcm[1] : (cg == 2) ? srcm[2] : srcm[3];
            int slane = msrc * 8 + dl;
            #pragma unroll
            for (int q = 0; q < 5; ++q)
                pcd[q] = __shfl_sync(0xffffffffu, pcd[q], slane);
            if (cg == newn) {
                #pragma unroll
                for (int q = 0; q < 5; ++q) pcd[q] = ctd[q];
            }

            // assign survivor slots + append candidate t at position newn
            if (newn == 0) { c0 = t; F0 = bv; S20 = U; }
            else           { c0 = nc0; F0 = nF0; S20 = nS0; }
            if (newn == 1) { c1 = t; F1 = bv; S21 = U; }
            else if (newn > 1) { c1 = nc1; F1 = nF1; S21 = nS1; }
            if (newn == 2) { c2 = t; F2 = bv; S22 = U; }
            else if (newn > 2) { c2 = nc2; F2 = nF2; S22 = nS2; }
            if (newn == 3) { c3 = t; F3 = bv; S23 = U; }
            else if (newn > 3) { c3 = nc3; F3 = nF3; S23 = nS3; }
            ncand = newn + 1;

            // keep smem candidate mirror for general-path entry (off chain)
            if (lane == 0) {
                s_cands[0] = (short)c0;
                if (ncand > 1) s_cands[1] = (short)c1;
                if (ncand > 2) s_cands[2] = (short)c2;
                if (ncand > 3) s_cands[3] = (short)c3;
                if (ncand > 4) s_cands[4] = (short)t;   // 5th = just-appended t
            }
            if (ncand > 4) { fast = false; __syncwarp(); }
        } else {
            // ---------- general smem path (R11, proven) ----------
            double S2t = U;
            for (int base = 0; base < ncand; base += 4) {
                int j = base + cg;
                double acc = 0.0;
                int c = 0;
                bool act2 = (j < ncand);
                if (act2) {
                    c = s_cands[j];
                    const double* pc = s_cs + c * 33;
                    #pragma unroll
                    for (int q = 0; q < 5; ++q) {
                        int d = dl + q * 8;
                        if (d < ND) {
                            double su = ctd[q] - pc[d];
                            acc = fma(su, su, acc);
                        }
                    }
                }
                acc += __shfl_down_sync(0xffffffffu, acc, 4);
                acc += __shfl_down_sync(0xffffffffu, acc, 2);
                acc += __shfl_down_sync(0xffffffffu, acc, 1);
                if (act2 && dl == 0) {
                    double cost = (S2t - s_s2[c]) - acc * s_recip[t - c];
                    s_vals[j] = s_Fc[c] + cost + PEN;
                }
            }
            __syncwarp();

            double bv = 1e300; int bj = 1 << 30;
            for (int j = lane; j < ncand; j += 32) {
                double v = s_vals[j];
                if (v < bv) { bv = v; bj = j; }
            }
            #pragma unroll
            for (int o = 16; o; o >>= 1) {
                double ov = __shfl_down_sync(0xffffffffu, bv, o);
                int    oj = __shfl_down_sync(0xffffffffu, bj, o);
                if (ov < bv || (ov == bv && oj < bj)) { bv = ov; bj = oj; }
            }
            bv = __shfl_sync(0xffffffffu, bv, 0);
            bj = __shfl_sync(0xffffffffu, bj, 0);
            if (lane == 0) { s_Fc[t] = bv; s_prev[t] = s_cands[bj]; }
            __syncwarp();

            double thr = bv + PEN;
            int newn = 0;
            for (int base = 0; base < ncand; base += 32) {
                int j = base + lane;
                short cj = 0; bool keep = false;
                if (j < ncand) { cj = s_cands[j]; keep = (s_vals[j] <= thr); }
                unsigned msk = __ballot_sync(0xffffffffu, keep);
                int pos = newn + __popc(msk & ((1u << lane) - 1u));
                __syncwarp();
                if (keep) s_cands[pos] = cj;
                newn += __popc(msk);
                __syncwarp();
            }
            if (lane == 0) s_cands[newn] = (short)t;
            ncand = newn + 1;
            __syncwarp();

            if (ncand <= 4) {
                // refill register state, resume fast path
                c0 = s_cands[0];
                c1 = (ncand > 1) ? s_cands[1] : 0;
                c2 = (ncand > 2) ? s_cands[2] : 0;
                c3 = (ncand > 3) ? s_cands[3] : 0;
                F0 = s_Fc[c0]; S20 = s_s2[c0];
                F1 = (ncand > 1) ? s_Fc[c1] : 0.0; S21 = (ncand > 1) ? s_s2[c1] : 0.0;
                F2 = (ncand > 2) ? s_Fc[c2] : 0.0; S22 = (ncand > 2) ? s_s2[c2] : 0.0;
                F3 = (ncand > 3) ? s_Fc[c3] : 0.0; S23 = (ncand > 3) ? s_s2[c3] : 0.0;
                int cm = (cg == 0) ? c0 : (cg == 1) ? c1 : (cg == 2) ? c2 : c3;
                #pragma unroll
                for (int q = 0; q < 5; ++q) {
                    int d = dl + q * 8;
                    pcd[q] = (cg < ncand && d < ND) ? s_cs[cm * 33 + d] : 0.0;
                }
                fast = true;
                __syncwarp();
            }
        }
    }

    if (lane == 0) {
        short bps[NF + 1];
        int nb = 0, t = NF;
        while (t > 0) { bps[nb++] = (short)t; t = s_prev[t]; }
        int bnd[MAXSEG];
        int bc = 1; bnd[0] = 0;
        for (int ii = nb - 1; ii >= 1; --ii) {
            int k = bps[ii];
            int bpos = (k < NF) ? HOP * k : Ln;
            if (bpos > Ln) bpos = Ln;
            if (bpos - bnd[bc - 1] >= 8 && bc < MAXSEG - 1) bnd[bc++] = bpos;
        }
        if (Ln - bnd[bc - 1] < 8 && bc > 1) bc--;
        bnd[bc++] = Ln;
        int nseg = bc - 1;
        int off = 0;
        for (int s = 0; s < nseg; ++s) {
            g_seg_s[b][s]   = bnd[s];
            g_seg_e[b][s]   = bnd[s + 1];
            g_seg_off[b][s] = off;
            off += (bnd[s + 1] - bnd[s]) >> 1;
        }
        g_nseg[b] = nseg;
    }
}

// ---- 5) fused: fp32 pairwise mean + DS-Goertzel + stats (warp/segment) -----
__global__ void k_segspec() {
    __shared__ float buf[4][SEGBUF];
    int b = blockIdx.y;
    int wid = threadIdx.x >> 5, lane = threadIdx.x & 31;
    int nseg = g_nseg[b];
    int wg = blockIdx.x * 4 + wid;
    int nwarp = gridDim.x * 4;
    float* wb = buf[wid];

    for (int seg = wg; seg < nseg; seg += nwarp) {
        int s = g_seg_s[b][seg], e = g_seg_e[b][seg];
        int n = e - s, nf = n >> 1;
        const float* sp = &g_sig[b][s];

        float mean = 0.0f;
        if (lane == 0) mean = __fdiv_rn(np_pairwise_sum(sp, n), (float)n);
        mean = __shfl_sync(0xffffffffu, mean, 0);

        bool small = (n <= SEGBUF);
        __syncwarp();
        if (small)
            for (int t = lane; t < n; t += 32) wb[t] = sp[t] - mean;
        __syncwarp();

        double pw[16];
        int nb = 0;
        double tot = 0.0, mv = -1.0; int mk = 1 << 30;

        for (int k = lane + 1; k <= nf; k += 32) {
            DS coeff;
            if (n == 32) { float2 cc = c_c32[k]; coeff = {cc.x, cc.y}; }
            else coeff = ds_from_d(2.0 * cos(2.0 * PI_D * (double)k / (double)n));

            DS s1 = {0.f, 0.f}, s2 = {0.f, 0.f};
            if (small) {
                for (int t = 0; t < n; ++t) {
                    DS t1 = ds_add({wb[t], 0.f}, ds_neg(s2));
                    DS sn = ds_add(t1, ds_mul(coeff, s1));
                    s2 = s1; s1 = sn;
                }
            } else {
                for (int t = 0; t < n; ++t) {
                    float v = sp[t] - mean;
                    DS t1 = ds_add({v, 0.f}, ds_neg(s2));
                    DS sn = ds_add(t1, ds_mul(coeff, s1));
                    s2 = s1; s1 = sn;
                }
            }
            DS aa = ds_mul(s1, s1);
            DS bb = ds_mul(s2, s2);
            DS cc = ds_mul(ds_mul(coeff, s1), s2);
            DS pp = ds_add(ds_add(aa, bb), ds_neg(cc));
            double pwv = (double)pp.hi + (double)pp.lo;
            if (pwv < 0.0) pwv = 0.0;
            if (small) pw[nb] = pwv;
            else g_spec[b][g_seg_off[b][seg] + (k - 1)] = pwv;
            ++nb;
            tot += pwv;
            if (pwv > mv) { mv = pwv; mk = k; }
        }
        __syncwarp();

        #pragma unroll
        for (int o = 16; o; o >>= 1) {
            tot += __shfl_down_sync(0xffffffffu, tot, o);
            double ov = __shfl_down_sync(0xffffffffu, mv, o);
            int    ok = __shfl_down_sync(0xffffffffu, mk, o);
            if (ov > mv || (ov == mv && ok < mk)) { mv = ov; mk = ok; }
        }
        tot = __shfl_sync(0xffffffffu, tot, 0);
        mk  = __shfl_sync(0xffffffffu, mk, 0);

        double dpv, bwvv;
        if (tot <= 0.0 || nf < 1) {
            dpv = (double)n; bwvv = 0.0;
        } else {
            double invtot = 1.0 / tot, invnf = 1.0 / (double)nf;
            double cacc = 0.0;
            { int i2 = 0;
              for (int k = lane + 1; k <= nf; k += 32) {
                  double v = small ? pw[i2++] : g_spec[b][g_seg_off[b][seg] + (k - 1)];
                  cacc += (v * invtot) * ((double)k * invnf);
              } }
            #pragma unroll
            for (int o = 16; o; o >>= 1) cacc += __shfl_down_sync(0xffffffffu, cacc, o);
            cacc = __shfl_sync(0xffffffffu, cacc, 0);

            double bacc = 0.0;
            { int i2 = 0;
              for (int k = lane + 1; k <= nf; k += 32) {
                  double v = small ? pw[i2++] : g_spec[b][g_seg_off[b][seg] + (k - 1)];
                  double fd = (double)k * invnf - cacc;
                  bacc += (v * invtot) * fd * fd;
              } }
            #pragma unroll
            for (int o = 16; o; o >>= 1) bacc += __shfl_down_sync(0xffffffffu, bacc, o);
            bacc = __shfl_sync(0xffffffffu, bacc, 0);

            dpv  = (double)n / (double)mk;
            bwvv = sqrt(bacc);
        }

        if (lane == 0) {
            g_dp[b][seg]  = dpv;
            g_bwv[b][seg] = bwvv;
            double raw = dpv / (1.0 + bwvv);
            double r = rint(raw * 0.5);
            int pl = (int)(2.0 * r);
            pl = pl < 8 ? 8 : (pl > 64 ? 64 : pl);
            g_pl[b][seg] = pl;
        }
        __syncwarp();
    }
}

// ------------------------- 6) token build (scan) ----------------------------
__global__ void k_tokens() {
    __shared__ int cnt[512];
    int b = blockIdx.x, tid = threadIdx.x;
    int nseg = g_nseg[b];
    int c = 0, s = 0, e = 0, pl = 8;
    if (tid < nseg) {
        s = g_seg_s[b][tid]; e = g_seg_e[b][tid]; pl = g_pl[b][tid];
        int len = e - s;
        int nfl = len / pl;
        c = nfl + ((len - nfl * pl) > 0 ? 1 : 0);
    }
    cnt[tid] = c;
    __syncthreads();
    for (int o = 1; o < 512; o <<= 1) {
        int v = cnt[tid];
        if (tid >= o) v += cnt[tid - o];
        __syncthreads();
        cnt[tid] = v;
        __syncthreads();
    }
    if (tid < nseg) {
        int off = cnt[tid] - c;
        int len = e - s;
        int nfl = len / pl;
        for (int i = 0; i < nfl; ++i) {
            g_tok_s[b][off + i]   = s + i * pl;
            g_tok_e[b][off + i]   = s + (i + 1) * pl;
            g_tok_seg[b][off + i] = tid;
        }
        if (nfl * pl < len) {
            g_tok_s[b][off + nfl]   = s + nfl * pl;
            g_tok_e[b][off + nfl]   = e;
            g_tok_seg[b][off + nfl] = tid;
        }
    }
    if (tid == 0) g_ntok[b] = cnt[511];
}

// -------------------------- 7a) scalar outputs ------------------------------
__global__ void k_scalars(float* __restrict__ o_mask, float* __restrict__ o_start,
                          float* __restrict__ o_end, float* __restrict__ o_center,
                          float* __restrict__ o_span, float* __restrict__ o_regime,
                          int mt) {
    int i = blockIdx.x * blockDim.x + threadIdx.x;
    int b = blockIdx.y;
    if (i >= mt) return;
    float m = 0.f, st = 0.f, en = 0.f, ce = 0.f, sp = 0.f, r0 = 0.f, r1 = 0.f, r2 = 0.f;
    if (i < g_ntok[b]) {
        int s = g_tok_s[b][i], e = g_tok_e[b][i], seg = g_tok_seg[b][i];
        m = 1.0f;
        st = (float)s; en = (float)e;
        ce = ((float)s + (float)e - 1.0f) * 0.5f / 16383.0f;
        sp = (float)(e - s) / 16384.0f;
        int sl = g_seg_e[b][seg] - g_seg_s[b][seg];
        r0 = (float)(g_dp[b][seg] / 16384.0);
        r1 = (float)g_bwv[b][seg];
        r2 = (float)((double)sl / 16384.0);
    }
    size_t idx = (size_t)b * mt + i;
    o_mask[idx] = m; o_start[idx] = st; o_end[idx] = en;
    o_center[idx] = ce; o_span[idx] = sp;
    o_regime[idx * 3 + 0] = r0;
    o_regime[idx * 3 + 1] = r1;
    o_regime[idx * 3 + 2] = r2;
}

__global__ void k_ntok(float* __restrict__ o_ntok) {
    int b = threadIdx.x;
    if (b < Bn) o_ntok[b] = (float)g_ntok[b];
}

// ---- 7b) patches (gather + lerp) g_x -> d_out, float4 stores ---------------
__global__ __launch_bounds__(256) void k_patches(float* __restrict__ o_patch, int mt) {
    int b = blockIdx.y;
    int tok = blockIdx.x * 2 + (threadIdx.x >> 7);
    int r = threadIdx.x & 127;
    int c = r >> 2, q = r & 3;
    if (tok >= mt) return;

    size_t obase = (((size_t)b * mt + tok) * Cn + c) * ANCH + q * 4;
    float4 v = make_float4(0.f, 0.f, 0.f, 0.f);
    if (tok < g_ntok[b]) {
        int s = g_tok_s[b][tok], e = g_tok_e[b][tok];
        int il = e - s;
        float scale = (float)il / 16.0f;
        const float* row = g_x[b][c] + s;
        float o[4];
        #pragma unroll
        for (int jj = 0; jj < 4; ++jj) {
            int j = q * 4 + jj;
            float coord = ((float)j + 0.5f) * scale - 0.5f;
            coord = fminf(fmaxf(coord, 0.0f), (float)(il - 1));
            int l = (int)floorf(coord);
            int h = min(l + 1, il - 1);
            float w = coord - (float)l;
            o[jj] = row[l] * (1.0f - w) + row[h] * w;
        }
        v = make_float4(o[0], o[1], o[2], o[3]);
    }
    *(float4*)(o_patch + obase) = v;
}

// --------------------------------- launch -----------------------------------
extern "C" void kernel_launch(void* const* d_in, const int* in_sizes, int n_in,
                              void* d_out, int out_size) {
    const float* x = (const float*)d_in[0];
    float* out = (float*)d_out;

    long long mt_ll = ((long long)out_size - Bn) / (16384 + 5 * Bn + 3 * Bn);
    if (mt_ll < 1) mt_ll = 1;
    int mt = (int)mt_ll;

    float* o_patch  = out;
    float* o_mask   = out + (size_t)Bn * mt * Cn * ANCH;
    float* o_start  = o_mask   + (size_t)Bn * mt;
    float* o_end    = o_start  + (size_t)Bn * mt;
    float* o_center = o_end    + (size_t)Bn * mt;
    float* o_span   = o_center + (size_t)Bn * mt;
    float* o_regime = o_span   + (size_t)Bn * mt;
    float* o_ntok   = o_regime + (size_t)Bn * mt * 3;

    static bool attr_done = false;
    if (!attr_done) {
        cudaFuncSetAttribute(k_pelt, cudaFuncAttributeMaxDynamicSharedMemorySize,
                             (int)PELT_SMEM);
        attr_done = true;
    }

    k_init<<<1, 512>>>();
    k_sig<<<dim3(16, Bn), 256>>>(x);
    k_feats<<<dim3(NF, Bn), WIN>>>();
    k_prefix<<<dim3(ND, Bn), 32>>>();
    k_s2<<<Bn, NF + 1>>>();
    k_pelt<<<Bn, 256, PELT_SMEM>>>();
    k_segspec<<<dim3(128, Bn), 128>>>();
    k_tokens<<<Bn, 512>>>();
    k_scalars<<<dim3((mt + 255) / 256, Bn), 256>>>(o_mask, o_start, o_end,
                                                   o_center, o_span, o_regime, mt);
    k_ntok<<<1, Bn>>>(o_ntok);
    k_patches<<<dim3((mt + 1) / 2, Bn), 256>>>(o_patch, mt);
}

// round 13
// speedup vs baseline: 1.1143x; 1.1143x over previous
#include <cuda_runtime.h>
#include <math.h>

namespace {
constexpr int    Bn = 32, Cn = 32, Ln = 16384, WIN = 64, HOP = 32;
constexpr int    NF = 511, ND = 33;
constexpr double PEN = 5.0;
constexpr int    MAXSEG = 520, MAXTOK = 4608, ANCH = 16;
constexpr double PI_D = 3.14159265358979323846264338327950288;
constexpr int    SEGBUF = 1024;
// k_pelt dynamic smem layout (doubles): cs 16896 | s2 512 | Fc 512 | vals 512 | recip 512
constexpr int    PELT_DBL  = 16896 + 512 + 512 + 512 + 512;
constexpr size_t PELT_SMEM = PELT_DBL * 8 + (512 + 514) * 2 + 16;
}

// ------------------------------- scratch ----------------------------------
__device__ float  g_x[Bn][Cn][Ln];
__device__ float  g_sig[Bn][Ln];
__device__ double g_feats[Bn][NF][ND];
__device__ double g_cs [Bn][NF + 1][ND];
__device__ double g_cs2[Bn][NF + 1][ND];
__device__ double g_s2 [Bn][NF + 1];
__device__ int    g_nseg[Bn];
__device__ int    g_seg_s[Bn][MAXSEG];
__device__ int    g_seg_e[Bn][MAXSEG];
__device__ int    g_seg_off[Bn][MAXSEG];
__device__ double g_spec[Bn][Ln / 2 + 8];
__device__ double g_dp[Bn][MAXSEG];
__device__ double g_bwv[Bn][MAXSEG];
__device__ int    g_pl[Bn][MAXSEG];
__device__ int    g_ntok[Bn];
__device__ int    g_tok_s[Bn][MAXTOK];
__device__ int    g_tok_e[Bn][MAXTOK];
__device__ int    g_tok_seg[Bn][MAXTOK];

// precomputed constants
__device__ float2 c_tw_re[WIN], c_tw_im[WIN], c_win[WIN];
__device__ float2 c_c32[17];
__device__ float2 c_lnc[11];
__device__ float2 c_ln2;
__device__ float2 c_eps;
__device__ double c_recip[NF + 1];

// ---------------------------- double-single ops ----------------------------
struct DS { float hi, lo; };
__device__ __forceinline__ DS two_sum(float a, float b) {
    float s = a + b, bb = s - a;
    float e = (a - (s - bb)) + (b - bb);
    return {s, e};
}
__device__ __forceinline__ DS quick2(float a, float b) {
    float s = a + b;
    return {s, b - (s - a)};
}
__device__ __forceinline__ DS ds_add(DS a, DS b) {
    DS s = two_sum(a.hi, b.hi);
    return quick2(s.hi, s.lo + a.lo + b.lo);
}
__device__ __forceinline__ DS ds_mul(DS a, DS b) {
    float p = a.hi * b.hi;
    float e = fmaf(a.hi, b.hi, -p);
    e = fmaf(a.hi, b.lo, e);
    e = fmaf(a.lo, b.hi, e);
    return quick2(p, e);
}
__device__ __forceinline__ DS ds_neg(DS a) { return {-a.hi, -a.lo}; }
__device__ __forceinline__ DS ds_from_d(double v) {
    float hi = (float)v;
    return {hi, (float)(v - (double)hi)};
}

// DS natural log; v > 0 well inside float range. abs err ~1e-13.
__device__ DS ds_log(DS v) {
    int e;
    float mh = frexpf(v.hi, &e);
    if (mh < 0.7071067811865476f) e -= 1;
    float sc = ldexpf(1.0f, -e);
    DS m = {v.hi * sc, v.lo * sc};
    DS num = ds_add(m, {-1.0f, 0.0f});
    DS den = ds_add(m, { 1.0f, 0.0f});
    float r = 1.0f / den.hi;
    float q1 = num.hi * r;
    DS t  = ds_add(num, ds_neg(ds_mul(den, {q1, 0.f})));
    float q2 = t.hi * r;
    DS t2 = ds_add(t,  ds_neg(ds_mul(den, {q2, 0.f})));
    float q3 = t2.hi * r;
    DS z = ds_add(ds_add({q1, 0.f}, {q2, 0.f}), {q3, 0.f});
    DS w = ds_mul(z, z);
    DS p = {c_lnc[10].x, c_lnc[10].y};
    #pragma unroll
    for (int k = 9; k >= 0; --k)
        p = ds_add(ds_mul(p, w), {c_lnc[k].x, c_lnc[k].y});
    DS lnm = ds_mul(ds_mul({2.0f, 0.f}, z), p);
    return ds_add(ds_mul({(float)e, 0.f}, {c_ln2.x, c_ln2.y}), lnm);
}

// numpy pairwise sum (float32), exact replication
__device__ float np_pairwise_sum(const float* a, int n) {
    if (n < 8) {
        float r = 0.0f;
        for (int i = 0; i < n; ++i) r += a[i];
        return r;
    } else if (n <= 128) {
        float r[8];
        #pragma unroll
        for (int j = 0; j < 8; ++j) r[j] = a[j];
        int i = 8;
        for (; i < n - (n % 8); i += 8) {
            #pragma unroll
            for (int j = 0; j < 8; ++j) r[j] += a[i + j];
        }
        float res = ((r[0] + r[1]) + (r[2] + r[3])) + ((r[4] + r[5]) + (r[6] + r[7]));
        for (; i < n; ++i) res += a[i];
        return res;
    } else {
        int n2 = n / 2;
        n2 -= n2 % 8;
        return np_pairwise_sum(a, n2) + np_pairwise_sum(a + n2, n - n2);
    }
}

// ------------------------------ 0) init ------------------------------------
__global__ void k_init() {
    int i = threadIdx.x;
    if (i < WIN) {
        double ang = -2.0 * PI_D * (double)i / 64.0;
        double sn, co;
        sincos(ang, &sn, &co);
        DS a = ds_from_d(co), b = ds_from_d(sn);
        c_tw_re[i] = make_float2(a.hi, a.lo);
        c_tw_im[i] = make_float2(b.hi, b.lo);
        DS wd = ds_from_d(0.5 - 0.5 * cos(2.0 * PI_D * (double)i / 63.0));
        c_win[i] = make_float2(wd.hi, wd.lo);
    }
    if (i <= 16) {
        DS c = ds_from_d(2.0 * cos(2.0 * PI_D * (double)i / 32.0));
        c_c32[i] = make_float2(c.hi, c.lo);
    }
    if (i <= 10) {
        DS c = ds_from_d(1.0 / (double)(2 * i + 1));
        c_lnc[i] = make_float2(c.hi, c.lo);
    }
    if (i == 0) {
        DS l2 = ds_from_d(0.69314718055994530941723212145818);
        c_ln2 = make_float2(l2.hi, l2.lo);
        DS ep = ds_from_d(1e-8);
        c_eps = make_float2(ep.hi, ep.lo);
    }
    if (i <= NF) c_recip[i] = i ? 1.0 / (double)i : 0.0;
}

// -------- 1) stage x -> g_x (HBM) + channel mean (float4 streaming) ---------
__global__ void k_sig(const float* __restrict__ x) {
    int t4 = blockIdx.x * blockDim.x + threadIdx.x;
    int b = blockIdx.y;
    if (t4 >= Ln / 4) return;
    const float4* p = (const float4*)(x + (size_t)b * Cn * Ln) + t4;
    float4 s = make_float4(0.f, 0.f, 0.f, 0.f);
    #pragma unroll
    for (int c = 0; c < Cn; ++c) {
        float4 v = p[(size_t)c * (Ln / 4)];
        ((float4*)g_x[b][c])[t4] = v;
        s.x += v.x; s.y += v.y; s.z += v.z; s.w += v.w;
    }
    s.x *= 0.03125f; s.y *= 0.03125f; s.z *= 0.03125f; s.w *= 0.03125f;
    ((float4*)g_sig[b])[t4] = s;
}

// ------------- 2) spectrogram features (DS fp32 DFT + DS log) --------------
__global__ void k_feats() {
    __shared__ float2 sv[WIN];
    __shared__ float2 twr[WIN], twi[WIN];
    __shared__ float  fr[WIN];
    __shared__ float  smean;
    int b = blockIdx.y, f = blockIdx.x, i = threadIdx.x;

    twr[i] = c_tw_re[i]; twi[i] = c_tw_im[i];
    fr[i] = g_sig[b][f * HOP + i];
    __syncthreads();

    if (i == 0) {
        float r[8];
        #pragma unroll
        for (int j = 0; j < 8; ++j) r[j] = fr[j];
        for (int o = 8; o < 64; o += 8) {
            #pragma unroll
            for (int j = 0; j < 8; ++j) r[j] += fr[o + j];
        }
        float s = ((r[0] + r[1]) + (r[2] + r[3])) + ((r[4] + r[5]) + (r[6] + r[7]));
        smean = s / 64.0f;
    }
    __syncthreads();

    {
        float d = fr[i] - smean;
        float2 w = c_win[i];
        float p = d * w.x;
        float e = fmaf(d, w.x, -p);
        e = fmaf(d, w.y, e);
        DS r = quick2(p, e);
        sv[i] = make_float2(r.hi, r.lo);
    }
    __syncthreads();

    if (i < ND) {
        DS re = {0.f, 0.f}, im = {0.f, 0.f};
        #pragma unroll 4
        for (int t = 0; t < WIN; ++t) {
            int m = (i * t) & 63;
            DS v  = {sv[t].x, sv[t].y};
            DS cr = {twr[m].x, twr[m].y};
            DS ci = {twi[m].x, twi[m].y};
            re = ds_add(re, ds_mul(v, cr));
            im = ds_add(im, ds_mul(v, ci));
        }
        DS p2 = ds_add(ds_mul(re, re), ds_mul(im, im));
        p2 = ds_add(p2, {c_eps.x, c_eps.y});
        DS lg = ds_log(p2);
        g_feats[b][f][i] = (double)lg.hi + (double)lg.lo;
    }
}

// -------- 3a) prefix sums: warp-per-(d,b) Kogge-Stone scan with carry -------
__global__ void k_prefix() {
    int d = blockIdx.x, b = blockIdx.y, lane = threadIdx.x;
    double carry = 0.0, carry2 = 0.0;
    if (lane == 0) { g_cs[b][0][d] = 0.0; g_cs2[b][0][d] = 0.0; }
    for (int base = 0; base < NF; base += 32) {
        int t = base + lane;
        double v  = (t < NF) ? g_feats[b][t][d] : 0.0;
        double v2 = v * v;
        #pragma unroll
        for (int o = 1; o < 32; o <<= 1) {
            double n1 = __shfl_up_sync(0xffffffffu, v,  o);
            double n2 = __shfl_up_sync(0xffffffffu, v2, o);
            if (lane >= o) { v += n1; v2 += n2; }
        }
        v += carry; v2 += carry2;
        if (t < NF) {
            g_cs[b][t + 1][d]  = v;
            g_cs2[b][t + 1][d] = v2;
        }
        carry  = __shfl_sync(0xffffffffu, v, 31);
        carry2 = __shfl_sync(0xffffffffu, v2, 31);
    }
}

// -------- 3b) S2 totals: sum over d of cs2 ----------------------------------
__global__ void k_s2() {
    int b = blockIdx.x, t = threadIdx.x;
    double s = 0.0;
    #pragma unroll
    for (int dd = 0; dd < ND; ++dd) s += g_cs2[b][t][dd];
    g_s2[b][t] = s;
}

// ------ 4) PELT DP: warp/batch, 8 candidate groups x 4 dim lanes ------------
__global__ void k_pelt() {
    extern __shared__ double dyn[];
    double* s_cs    = dyn;                 // 16896 = 512*33
    double* s_s2    = dyn + 16896;         // 512
    double* s_Fc    = dyn + 17408;         // 512
    double* s_vals  = dyn + 17920;         // 512
    double* s_recip = dyn + 18432;         // 512
    short*  s_prev  = (short*)(dyn + 18944);        // 512 shorts
    short*  s_cands = s_prev + 512;                 // 514 shorts

    int b = blockIdx.x, tid = threadIdx.x;

    const double* gc = (const double*)g_cs[b];
    for (int i = tid; i < 16896; i += 256) s_cs[i] = gc[i];
    for (int i = tid; i < 512;   i += 256) {
        s_s2[i]    = g_s2[b][i];
        s_recip[i] = c_recip[i];
    }
    __syncthreads();
    if (tid >= 32) return;

    int lane = tid;
    int cg = lane >> 2;   // candidate group (0..7)
    int dl = lane & 3;    // dim lane (0..3)
    if (lane == 0) { s_Fc[0] = -PEN; s_cands[0] = 0; }
    int ncand = 1;
    __syncwarp();

    for (int t = 1; t <= NF; ++t) {
        const double* ct = s_cs + t * 33;
        double S2t = s_s2[t];
        double ctd[9];
        #pragma unroll
        for (int q = 0; q < 9; ++q) {
            int d = dl + q * 4;
            ctd[q] = (d < ND) ? ct[d] : 0.0;
        }

        if (ncand <= 8) {
            // -------- single-pass fast path: no s_vals round-trip --------
            int j = cg;
            bool act = (j < ncand);
            int c = act ? s_cands[j] : 0;
            const double* pc = s_cs + c * 33;
            double a0 = 0.0, a1 = 0.0;
            if (act) {
                #pragma unroll
                for (int q = 0; q < 9; ++q) {
                    int d = dl + q * 4;
                    if (d < ND) {
                        double su = ctd[q] - pc[d];
                        if (q & 1) a1 = fma(su, su, a1);
                        else       a0 = fma(su, su, a0);
                    }
                }
            }
            double acc = a0 + a1;
            acc += __shfl_down_sync(0xffffffffu, acc, 2);
            acc += __shfl_down_sync(0xffffffffu, acc, 1);
            double val = 1e300;
            if (act && dl == 0) {
                double cost = (S2t - s_s2[c]) - acc * s_recip[t - c];
                val = s_Fc[c] + cost + PEN;
            }

            // uniform argmin over groups (strict < keeps first index)
            double bv = 1e300; int prevc = 0;
            #pragma unroll
            for (int jj = 0; jj < 8; ++jj) {
                double vj = __shfl_sync(0xffffffffu, val, jj * 4);
                int    cj = __shfl_sync(0xffffffffu, c,   jj * 4);
                if (jj < ncand && vj < bv) { bv = vj; prevc = cj; }
            }
            if (lane == 0) { s_Fc[t] = bv; s_prev[t] = (short)prevc; }

            // prune: ballot over owner lanes (bits at 4*j, ascending j)
            double thr = bv + PEN;
            bool keep = act && (dl == 0) && (val <= thr);
            unsigned msk = __ballot_sync(0xffffffffu, keep);
            if (keep) {
                int pos = __popc(msk & ((1u << lane) - 1u));
                s_cands[pos] = (short)c;
            }
            int newn = __popc(msk);
            if (lane == 0) s_cands[newn] = (short)t;
            ncand = newn + 1;
            __syncwarp();
        } else {
            // -------- general path: passes of 8 via s_vals --------
            for (int base = 0; base < ncand; base += 8) {
                int j = base + cg;
                double a0 = 0.0, a1 = 0.0;
                int c = 0;
                bool act = (j < ncand);
                if (act) {
                    c = s_cands[j];
                    const double* pc = s_cs + c * 33;
                    #pragma unroll
                    for (int q = 0; q < 9; ++q) {
                        int d = dl + q * 4;
                        if (d < ND) {
                            double su = ctd[q] - pc[d];
                            if (q & 1) a1 = fma(su, su, a1);
                            else       a0 = fma(su, su, a0);
                        }
                    }
                }
                double acc = a0 + a1;
                acc += __shfl_down_sync(0xffffffffu, acc, 2);
                acc += __shfl_down_sync(0xffffffffu, acc, 1);
                if (act && dl == 0) {
                    double cost = (S2t - s_s2[c]) - acc * s_recip[t - c];
                    s_vals[j] = s_Fc[c] + cost + PEN;
                }
            }
            __syncwarp();

            double bv = 1e300; int bj = 1 << 30;
            for (int j = lane; j < ncand; j += 32) {
                double v = s_vals[j];
                if (v < bv) { bv = v; bj = j; }
            }
            #pragma unroll
            for (int o = 16; o; o >>= 1) {
                double ov = __shfl_down_sync(0xffffffffu, bv, o);
                int    oj = __shfl_down_sync(0xffffffffu, bj, o);
                if (ov < bv || (ov == bv && oj < bj)) { bv = ov; bj = oj; }
            }
            bv = __shfl_sync(0xffffffffu, bv, 0);
            bj = __shfl_sync(0xffffffffu, bj, 0);
            if (lane == 0) { s_Fc[t] = bv; s_prev[t] = s_cands[bj]; }
            __syncwarp();

            double thr = bv + PEN;
            int newn = 0;
            for (int base = 0; base < ncand; base += 32) {
                int j = base + lane;
                short cj = 0; bool keep = false;
                if (j < ncand) { cj = s_cands[j]; keep = (s_vals[j] <= thr); }
                unsigned msk = __ballot_sync(0xffffffffu, keep);
                int pos = newn + __popc(msk & ((1u << lane) - 1u));
                __syncwarp();
                if (keep) s_cands[pos] = cj;
                newn += __popc(msk);
                __syncwarp();
            }
            if (lane == 0) s_cands[newn] = (short)t;
            ncand = newn + 1;
            __syncwarp();
        }
    }

    if (lane == 0) {
        short bps[NF + 1];
        int nb = 0, t = NF;
        while (t > 0) { bps[nb++] = (short)t; t = s_prev[t]; }
        int bnd[MAXSEG];
        int bc = 1; bnd[0] = 0;
        for (int ii = nb - 1; ii >= 1; --ii) {
            int k = bps[ii];
            int bpos = (k < NF) ? HOP * k : Ln;
            if (bpos > Ln) bpos = Ln;
            if (bpos - bnd[bc - 1] >= 8 && bc < MAXSEG - 1) bnd[bc++] = bpos;
        }
        if (Ln - bnd[bc - 1] < 8 && bc > 1) bc--;
        bnd[bc++] = Ln;
        int nseg = bc - 1;
        int off = 0;
        for (int s = 0; s < nseg; ++s) {
            g_seg_s[b][s]   = bnd[s];
            g_seg_e[b][s]   = bnd[s + 1];
            g_seg_off[b][s] = off;
            off += (bnd[s + 1] - bnd[s]) >> 1;
        }
        g_nseg[b] = nseg;
    }
}

// ---- 5) fused: fp32 pairwise mean + DS-Goertzel + stats (warp/segment) -----
__global__ void k_segspec() {
    __shared__ float buf[4][SEGBUF];
    int b = blockIdx.y;
    int wid = threadIdx.x >> 5, lane = threadIdx.x & 31;
    int nseg = g_nseg[b];
    int wg = blockIdx.x * 4 + wid;
    int nwarp = gridDim.x * 4;
    float* wb = buf[wid];

    for (int seg = wg; seg < nseg; seg += nwarp) {
        int s = g_seg_s[b][seg], e = g_seg_e[b][seg];
        int n = e - s, nf = n >> 1;
        const float* sp = &g_sig[b][s];

        float mean = 0.0f;
        if (lane == 0) mean = __fdiv_rn(np_pairwise_sum(sp, n), (float)n);
        mean = __shfl_sync(0xffffffffu, mean, 0);

        bool small = (n <= SEGBUF);
        __syncwarp();
        if (small)
            for (int t = lane; t < n; t += 32) wb[t] = sp[t] - mean;
        __syncwarp();

        double pw[16];
        int nb = 0;
        double tot = 0.0, mv = -1.0; int mk = 1 << 30;

        for (int k = lane + 1; k <= nf; k += 32) {
            DS coeff;
            if (n == 32) { float2 cc = c_c32[k]; coeff = {cc.x, cc.y}; }
            else coeff = ds_from_d(2.0 * cos(2.0 * PI_D * (double)k / (double)n));

            DS s1 = {0.f, 0.f}, s2 = {0.f, 0.f};
            if (small) {
                for (int t = 0; t < n; ++t) {
                    DS t1 = ds_add({wb[t], 0.f}, ds_neg(s2));
                    DS sn = ds_add(t1, ds_mul(coeff, s1));
                    s2 = s1; s1 = sn;
                }
            } else {
                for (int t = 0; t < n; ++t) {
                    float v = sp[t] - mean;
                    DS t1 = ds_add({v, 0.f}, ds_neg(s2));
                    DS sn = ds_add(t1, ds_mul(coeff, s1));
                    s2 = s1; s1 = sn;
                }
            }
            DS aa = ds_mul(s1, s1);
            DS bb = ds_mul(s2, s2);
            DS cc = ds_mul(ds_mul(coeff, s1), s2);
            DS pp = ds_add(ds_add(aa, bb), ds_neg(cc));
            double pwv = (double)pp.hi + (double)pp.lo;
            if (pwv < 0.0) pwv = 0.0;
            if (small) pw[nb] = pwv;
            else g_spec[b][g_seg_off[b][seg] + (k - 1)] = pwv;
            ++nb;
            tot += pwv;
            if (pwv > mv) { mv = pwv; mk = k; }
        }
        __syncwarp();

        #pragma unroll
        for (int o = 16; o; o >>= 1) {
            tot += __shfl_down_sync(0xffffffffu, tot, o);
            double ov = __shfl_down_sync(0xffffffffu, mv, o);
            int    ok = __shfl_down_sync(0xffffffffu, mk, o);
            if (ov > mv || (ov == mv && ok < mk)) { mv = ov; mk = ok; }
        }
        tot = __shfl_sync(0xffffffffu, tot, 0);
        mk  = __shfl_sync(0xffffffffu, mk, 0);

        double dpv, bwvv;
        if (tot <= 0.0 || nf < 1) {
            dpv = (double)n; bwvv = 0.0;
        } else {
            double invtot = 1.0 / tot, invnf = 1.0 / (double)nf;
            double cacc = 0.0;
            { int i2 = 0;
              for (int k = lane + 1; k <= nf; k += 32) {
                  double v = small ? pw[i2++] : g_spec[b][g_seg_off[b][seg] + (k - 1)];
                  cacc += (v * invtot) * ((double)k * invnf);
              } }
            #pragma unroll
            for (int o = 16; o; o >>= 1) cacc += __shfl_down_sync(0xffffffffu, cacc, o);
            cacc = __shfl_sync(0xffffffffu, cacc, 0);

            double bacc = 0.0;
            { int i2 = 0;
              for (int k = lane + 1; k <= nf; k += 32) {
                  double v = small ? pw[i2++] : g_spec[b][g_seg_off[b][seg] + (k - 1)];
                  double fd = (double)k * invnf - cacc;
                  bacc += (v * invtot) * fd * fd;
              } }
            #pragma unroll
            for (int o = 16; o; o >>= 1) bacc += __shfl_down_sync(0xffffffffu, bacc, o);
            bacc = __shfl_sync(0xffffffffu, bacc, 0);

            dpv  = (double)n / (double)mk;
            bwvv = sqrt(bacc);
        }

        if (lane == 0) {
            g_dp[b][seg]  = dpv;
            g_bwv[b][seg] = bwvv;
            double raw = dpv / (1.0 + bwvv);
            double r = rint(raw * 0.5);
            int pl = (int)(2.0 * r);
            pl = pl < 8 ? 8 : (pl > 64 ? 64 : pl);
            g_pl[b][seg] = pl;
        }
        __syncwarp();
    }
}

// ------------------------- 6) token build (scan) ----------------------------
__global__ void k_tokens() {
    __shared__ int cnt[512];
    int b = blockIdx.x, tid = threadIdx.x;
    int nseg = g_nseg[b];
    int c = 0, s = 0, e = 0, pl = 8;
    if (tid < nseg) {
        s = g_seg_s[b][tid]; e = g_seg_e[b][tid]; pl = g_pl[b][tid];
        int len = e - s;
        int nfl = len / pl;
        c = nfl + ((len - nfl * pl) > 0 ? 1 : 0);
    }
    cnt[tid] = c;
    __syncthreads();
    for (int o = 1; o < 512; o <<= 1) {
        int v = cnt[tid];
        if (tid >= o) v += cnt[tid - o];
        __syncthreads();
        cnt[tid] = v;
        __syncthreads();
    }
    if (tid < nseg) {
        int off = cnt[tid] - c;
        int len = e - s;
        int nfl = len / pl;
        for (int i = 0; i < nfl; ++i) {
            g_tok_s[b][off + i]   = s + i * pl;
            g_tok_e[b][off + i]   = s + (i + 1) * pl;
            g_tok_seg[b][off + i] = tid;
        }
        if (nfl * pl < len) {
            g_tok_s[b][off + nfl]   = s + nfl * pl;
            g_tok_e[b][off + nfl]   = e;
            g_tok_seg[b][off + nfl] = tid;
        }
    }
    if (tid == 0) g_ntok[b] = cnt[511];
}

// -------------------------- 7a) scalar outputs ------------------------------
__global__ void k_scalars(float* __restrict__ o_mask, float* __restrict__ o_start,
                          float* __restrict__ o_end, float* __restrict__ o_center,
                          float* __restrict__ o_span, float* __restrict__ o_regime,
                          int mt) {
    int i = blockIdx.x * blockDim.x + threadIdx.x;
    int b = blockIdx.y;
    if (i >= mt) return;
    float m = 0.f, st = 0.f, en = 0.f, ce = 0.f, sp = 0.f, r0 = 0.f, r1 = 0.f, r2 = 0.f;
    if (i < g_ntok[b]) {
        int s = g_tok_s[b][i], e = g_tok_e[b][i], seg = g_tok_seg[b][i];
        m = 1.0f;
        st = (float)s; en = (float)e;
        ce = ((float)s + (float)e - 1.0f) * 0.5f / 16383.0f;
        sp = (float)(e - s) / 16384.0f;
        int sl = g_seg_e[b][seg] - g_seg_s[b][seg];
        r0 = (float)(g_dp[b][seg] / 16384.0);
        r1 = (float)g_bwv[b][seg];
        r2 = (float)((double)sl / 16384.0);
    }
    size_t idx = (size_t)b * mt + i;
    o_mask[idx] = m; o_start[idx] = st; o_end[idx] = en;
    o_center[idx] = ce; o_span[idx] = sp;
    o_regime[idx * 3 + 0] = r0;
    o_regime[idx * 3 + 1] = r1;
    o_regime[idx * 3 + 2] = r2;
}

__global__ void k_ntok(float* __restrict__ o_ntok) {
    int b = threadIdx.x;
    if (b < Bn) o_ntok[b] = (float)g_ntok[b];
}

// ---- 7b) patches (gather + lerp) g_x -> d_out, float4 stores ---------------
__global__ __launch_bounds__(256) void k_patches(float* __restrict__ o_patch, int mt) {
    int b = blockIdx.y;
    int tok = blockIdx.x * 2 + (threadIdx.x >> 7);
    int r = threadIdx.x & 127;
    int c = r >> 2, q = r & 3;
    if (tok >= mt) return;

    size_t obase = (((size_t)b * mt + tok) * Cn + c) * ANCH + q * 4;
    float4 v = make_float4(0.f, 0.f, 0.f, 0.f);
    if (tok < g_ntok[b]) {
        int s = g_tok_s[b][tok], e = g_tok_e[b][tok];
        int il = e - s;
        float scale = (float)il / 16.0f;
        const float* row = g_x[b][c] + s;
        float o[4];
        #pragma unroll
        for (int jj = 0; jj < 4; ++jj) {
            int j = q * 4 + jj;
            float coord = ((float)j + 0.5f) * scale - 0.5f;
            coord = fminf(fmaxf(coord, 0.0f), (float)(il - 1));
            int l = (int)floorf(coord);
            int h = min(l + 1, il - 1);
            float w = coord - (float)l;
            o[jj] = row[l] * (1.0f - w) + row[h] * w;
        }
        v = make_float4(o[0], o[1], o[2], o[3]);
    }
    *(float4*)(o_patch + obase) = v;
}

// --------------------------------- launch -----------------------------------
extern "C" void kernel_launch(void* const* d_in, const int* in_sizes, int n_in,
                              void* d_out, int out_size) {
    const float* x = (const float*)d_in[0];
    float* out = (float*)d_out;

    long long mt_ll = ((long long)out_size - Bn) / (16384 + 5 * Bn + 3 * Bn);
    if (mt_ll < 1) mt_ll = 1;
    int mt = (int)mt_ll;

    float* o_patch  = out;
    float* o_mask   = out + (size_t)Bn * mt * Cn * ANCH;
    float* o_start  = o_mask   + (size_t)Bn * mt;
    float* o_end    = o_start  + (size_t)Bn * mt;
    float* o_center = o_end    + (size_t)Bn * mt;
    float* o_span   = o_center + (size_t)Bn * mt;
    float* o_regime = o_span   + (size_t)Bn * mt;
    float* o_ntok   = o_regime + (size_t)Bn * mt * 3;

    static bool attr_done = false;
    if (!attr_done) {
        cudaFuncSetAttribute(k_pelt, cudaFuncAttributeMaxDynamicSharedMemorySize,
                             (int)PELT_SMEM);
        attr_done = true;
    }

    k_init<<<1, 512>>>();
    k_sig<<<dim3(16, Bn), 256>>>(x);
    k_feats<<<dim3(NF, Bn), WIN>>>();
    k_prefix<<<dim3(ND, Bn), 32>>>();
    k_s2<<<Bn, NF + 1>>>();
    k_pelt<<<Bn, 256, PELT_SMEM>>>();
    k_segspec<<<dim3(128, Bn), 128>>>();
    k_tokens<<<Bn, 512>>>();
    k_scalars<<<dim3((mt + 255) / 256, Bn), 256>>>(o_mask, o_start, o_end,
                                                   o_center, o_span, o_regime, mt);
    k_ntok<<<1, Bn>>>(o_ntok);
    k_patches<<<dim3((mt + 1) / 2, Bn), 256>>>(o_patch, mt);
}

// round 14
// speedup vs baseline: 1.3241x; 1.1883x over previous
#include <cuda_runtime.h>
#include <math.h>

namespace {
constexpr int    Bn = 32, Cn = 32, Ln = 16384, WIN = 64, HOP = 32;
constexpr int    NF = 511, ND = 33;
constexpr double PEN = 5.0;
constexpr int    MAXSEG = 520, MAXTOK = 4608, ANCH = 16;
constexpr double PI_D = 3.14159265358979323846264338327950288;
constexpr int    SEGBUF = 1024;
constexpr int    PELT_DBL  = 16896 + 512 + 512 + 512 + 512;
constexpr size_t PELT_SMEM = PELT_DBL * 8 + (512 + 514) * 2 + 16;
}

// ------------------------------- scratch ----------------------------------
__device__ float  g_x[Bn][Cn][Ln];
__device__ float  g_sig[Bn][Ln];
__device__ double g_feats[Bn][NF][ND];
__device__ double g_cs [Bn][NF + 1][ND];
__device__ double g_cs2[Bn][NF + 1][ND];
__device__ double g_s2 [Bn][NF + 1];
__device__ int    g_nseg[Bn];
__device__ int    g_seg_s[Bn][MAXSEG];
__device__ int    g_seg_e[Bn][MAXSEG];
__device__ int    g_seg_off[Bn][MAXSEG];
__device__ double g_spec[Bn][Ln / 2 + 8];
__device__ double g_dp[Bn][MAXSEG];
__device__ double g_bwv[Bn][MAXSEG];
__device__ int    g_pl[Bn][MAXSEG];
__device__ int    g_ntok[Bn];
__device__ int    g_tok_s[Bn][MAXTOK];
__device__ int    g_tok_e[Bn][MAXTOK];
__device__ int    g_tok_seg[Bn][MAXTOK];

// precomputed constants
__device__ float2 c_tw_re[WIN], c_tw_im[WIN], c_win[WIN];
__device__ float2 c_c32[17];
__device__ float2 c_lnc[11];
__device__ float2 c_ln2;
__device__ float2 c_eps;
__device__ double c_recip[NF + 1];

// ---------------------------- double-single ops ----------------------------
struct DS { float hi, lo; };
__device__ __forceinline__ DS two_sum(float a, float b) {
    float s = a + b, bb = s - a;
    float e = (a - (s - bb)) + (b - bb);
    return {s, e};
}
__device__ __forceinline__ DS quick2(float a, float b) {
    float s = a + b;
    return {s, b - (s - a)};
}
__device__ __forceinline__ DS ds_add(DS a, DS b) {
    DS s = two_sum(a.hi, b.hi);
    return quick2(s.hi, s.lo + a.lo + b.lo);
}
__device__ __forceinline__ DS ds_mul(DS a, DS b) {
    float p = a.hi * b.hi;
    float e = fmaf(a.hi, b.hi, -p);
    e = fmaf(a.hi, b.lo, e);
    e = fmaf(a.lo, b.hi, e);
    return quick2(p, e);
}
__device__ __forceinline__ DS ds_neg(DS a) { return {-a.hi, -a.lo}; }
__device__ __forceinline__ DS ds_from_d(double v) {
    float hi = (float)v;
    return {hi, (float)(v - (double)hi)};
}

// DS natural log; v > 0 well inside float range. abs err ~1e-13.
__device__ DS ds_log(DS v) {
    int e;
    float mh = frexpf(v.hi, &e);
    if (mh < 0.7071067811865476f) e -= 1;
    float sc = ldexpf(1.0f, -e);
    DS m = {v.hi * sc, v.lo * sc};
    DS num = ds_add(m, {-1.0f, 0.0f});
    DS den = ds_add(m, { 1.0f, 0.0f});
    float r = 1.0f / den.hi;
    float q1 = num.hi * r;
    DS t  = ds_add(num, ds_neg(ds_mul(den, {q1, 0.f})));
    float q2 = t.hi * r;
    DS t2 = ds_add(t,  ds_neg(ds_mul(den, {q2, 0.f})));
    float q3 = t2.hi * r;
    DS z = ds_add(ds_add({q1, 0.f}, {q2, 0.f}), {q3, 0.f});
    DS w = ds_mul(z, z);
    DS p = {c_lnc[10].x, c_lnc[10].y};
    #pragma unroll
    for (int k = 9; k >= 0; --k)
        p = ds_add(ds_mul(p, w), {c_lnc[k].x, c_lnc[k].y});
    DS lnm = ds_mul(ds_mul({2.0f, 0.f}, z), p);
    return ds_add(ds_mul({(float)e, 0.f}, {c_ln2.x, c_ln2.y}), lnm);
}

// numpy pairwise sum (float32), exact replication
__device__ float np_pairwise_sum(const float* a, int n) {
    if (n < 8) {
        float r = 0.0f;
        for (int i = 0; i < n; ++i) r += a[i];
        return r;
    } else if (n <= 128) {
        float r[8];
        #pragma unroll
        for (int j = 0; j < 8; ++j) r[j] = a[j];
        int i = 8;
        for (; i < n - (n % 8); i += 8) {
            #pragma unroll
            for (int j = 0; j < 8; ++j) r[j] += a[i + j];
        }
        float res = ((r[0] + r[1]) + (r[2] + r[3])) + ((r[4] + r[5]) + (r[6] + r[7]));
        for (; i < n; ++i) res += a[i];
        return res;
    } else {
        int n2 = n / 2;
        n2 -= n2 % 8;
        return np_pairwise_sum(a, n2) + np_pairwise_sum(a + n2, n - n2);
    }
}

// ------------------------------ 0) init ------------------------------------
__global__ void k_init() {
    int i = threadIdx.x;
    if (i < WIN) {
        double ang = -2.0 * PI_D * (double)i / 64.0;
        double sn, co;
        sincos(ang, &sn, &co);
        DS a = ds_from_d(co), b = ds_from_d(sn);
        c_tw_re[i] = make_float2(a.hi, a.lo);
        c_tw_im[i] = make_float2(b.hi, b.lo);
        DS wd = ds_from_d(0.5 - 0.5 * cos(2.0 * PI_D * (double)i / 63.0));
        c_win[i] = make_float2(wd.hi, wd.lo);
    }
    if (i <= 16) {
        DS c = ds_from_d(2.0 * cos(2.0 * PI_D * (double)i / 32.0));
        c_c32[i] = make_float2(c.hi, c.lo);
    }
    if (i <= 10) {
        DS c = ds_from_d(1.0 / (double)(2 * i + 1));
        c_lnc[i] = make_float2(c.hi, c.lo);
    }
    if (i == 0) {
        DS l2 = ds_from_d(0.69314718055994530941723212145818);
        c_ln2 = make_float2(l2.hi, l2.lo);
        DS ep = ds_from_d(1e-8);
        c_eps = make_float2(ep.hi, ep.lo);
    }
    if (i <= NF) c_recip[i] = i ? 1.0 / (double)i : 0.0;
}

// -------- 1) stage x -> g_x (HBM) + channel mean (float4 streaming) ---------
__global__ void k_sig(const float* __restrict__ x) {
    int t4 = blockIdx.x * blockDim.x + threadIdx.x;
    int b = blockIdx.y;
    if (t4 >= Ln / 4) return;
    const float4* p = (const float4*)(x + (size_t)b * Cn * Ln) + t4;
    float4 s = make_float4(0.f, 0.f, 0.f, 0.f);
    #pragma unroll
    for (int c = 0; c < Cn; ++c) {
        float4 v = p[(size_t)c * (Ln / 4)];
        ((float4*)g_x[b][c])[t4] = v;
        s.x += v.x; s.y += v.y; s.z += v.z; s.w += v.w;
    }
    s.x *= 0.03125f; s.y *= 0.03125f; s.z *= 0.03125f; s.w *= 0.03125f;
    ((float4*)g_sig[b])[t4] = s;
}

// ------ 2) spectrogram features (DS fp32 DFT, 4 independent chains) --------
__global__ void k_feats() {
    __shared__ float2 sv[WIN];
    __shared__ float2 twr[WIN], twi[WIN];
    __shared__ float  fr[WIN];
    __shared__ float  smean;
    int b = blockIdx.y, f = blockIdx.x, i = threadIdx.x;

    twr[i] = c_tw_re[i]; twi[i] = c_tw_im[i];
    fr[i] = g_sig[b][f * HOP + i];
    __syncthreads();

    if (i == 0) {
        float r[8];
        #pragma unroll
        for (int j = 0; j < 8; ++j) r[j] = fr[j];
        for (int o = 8; o < 64; o += 8) {
            #pragma unroll
            for (int j = 0; j < 8; ++j) r[j] += fr[o + j];
        }
        float s = ((r[0] + r[1]) + (r[2] + r[3])) + ((r[4] + r[5]) + (r[6] + r[7]));
        smean = s / 64.0f;
    }
    __syncthreads();

    {
        float d = fr[i] - smean;
        float2 w = c_win[i];
        float p = d * w.x;
        float e = fmaf(d, w.x, -p);
        e = fmaf(d, w.y, e);
        DS r = quick2(p, e);
        sv[i] = make_float2(r.hi, r.lo);
    }
    __syncthreads();

    if (i < ND) {
        DS re0 = {0.f, 0.f}, re1 = {0.f, 0.f};
        DS im0 = {0.f, 0.f}, im1 = {0.f, 0.f};
        #pragma unroll 4
        for (int t = 0; t < WIN; t += 2) {
            int m0 = (i * t) & 63;
            int m1 = (i * (t + 1)) & 63;
            DS v0 = {sv[t].x, sv[t].y};
            DS v1 = {sv[t + 1].x, sv[t + 1].y};
            re0 = ds_add(re0, ds_mul(v0, {twr[m0].x, twr[m0].y}));
            im0 = ds_add(im0, ds_mul(v0, {twi[m0].x, twi[m0].y}));
            re1 = ds_add(re1, ds_mul(v1, {twr[m1].x, twr[m1].y}));
            im1 = ds_add(im1, ds_mul(v1, {twi[m1].x, twi[m1].y}));
        }
        DS re = ds_add(re0, re1);
        DS im = ds_add(im0, im1);
        DS p2 = ds_add(ds_mul(re, re), ds_mul(im, im));
        p2 = ds_add(p2, {c_eps.x, c_eps.y});
        DS lg = ds_log(p2);
        g_feats[b][f][i] = (double)lg.hi + (double)lg.lo;
    }
}

// -------- 3a) prefix sums: warp-per-(d,b) Kogge-Stone scan with carry -------
__global__ void k_prefix() {
    int d = blockIdx.x, b = blockIdx.y, lane = threadIdx.x;
    double carry = 0.0, carry2 = 0.0;
    if (lane == 0) { g_cs[b][0][d] = 0.0; g_cs2[b][0][d] = 0.0; }
    for (int base = 0; base < NF; base += 32) {
        int t = base + lane;
        double v  = (t < NF) ? g_feats[b][t][d] : 0.0;
        double v2 = v * v;
        #pragma unroll
        for (int o = 1; o < 32; o <<= 1) {
            double n1 = __shfl_up_sync(0xffffffffu, v,  o);
            double n2 = __shfl_up_sync(0xffffffffu, v2, o);
            if (lane >= o) { v += n1; v2 += n2; }
        }
        v += carry; v2 += carry2;
        if (t < NF) {
            g_cs[b][t + 1][d]  = v;
            g_cs2[b][t + 1][d] = v2;
        }
        carry  = __shfl_sync(0xffffffffu, v, 31);
        carry2 = __shfl_sync(0xffffffffu, v2, 31);
    }
}

// -------- 3b) S2 totals: sum over d of cs2 ----------------------------------
__global__ void k_s2() {
    int b = blockIdx.x, t = threadIdx.x;
    double s = 0.0;
    #pragma unroll
    for (int dd = 0; dd < ND; ++dd) s += g_cs2[b][t][dd];
    g_s2[b][t] = s;
}

// ------ 4) PELT DP: R11 structure (proven), dual accumulators only ----------
__global__ void k_pelt() {
    extern __shared__ double dyn[];
    double* s_cs    = dyn;                 // 16896 = 512*33
    double* s_s2    = dyn + 16896;         // 512
    double* s_Fc    = dyn + 17408;         // 512
    double* s_vals  = dyn + 17920;         // 512
    double* s_recip = dyn + 18432;         // 512
    short*  s_prev  = (short*)(dyn + 18944);        // 512 shorts
    short*  s_cands = s_prev + 512;                 // 514 shorts

    int b = blockIdx.x, tid = threadIdx.x;

    const double* gc = (const double*)g_cs[b];
    for (int i = tid; i < 16896; i += 256) s_cs[i] = gc[i];
    for (int i = tid; i < 512;   i += 256) {
        s_s2[i]    = g_s2[b][i];
        s_recip[i] = c_recip[i];
    }
    __syncthreads();
    if (tid >= 32) return;

    int lane = tid;
    int cg = lane >> 3;   // candidate slot within pass (0..3)
    int dl = lane & 7;    // dim lane (0..7)
    if (lane == 0) { s_Fc[0] = -PEN; s_cands[0] = 0; }
    int ncand = 1;
    __syncwarp();

    for (int t = 1; t <= NF; ++t) {
        const double* ct = s_cs + t * 33;
        double S2t = s_s2[t];
        double ctd[5];
        #pragma unroll
        for (int q = 0; q < 5; ++q) {
            int d = dl + q * 8;
            ctd[q] = (d < ND) ? ct[d] : 0.0;
        }

        if (ncand <= 4) {
            // ---------- register fast path (R11) with dual accumulators ----
            int j = cg;
            double val = 1e300;
            int c = 0;
            bool act = (j < ncand);
            if (act) c = s_cands[j];
            {
                const double* pc = s_cs + c * 33;
                double a0 = 0.0, a1 = 0.0;
                if (act) {
                    double s0 = ctd[0] - pc[dl];      a0 = fma(s0, s0, a0);
                    double s1 = ctd[1] - pc[dl + 8];  a1 = fma(s1, s1, a1);
                    double s2 = ctd[2] - pc[dl + 16]; a0 = fma(s2, s2, a0);
                    double s3 = ctd[3] - pc[dl + 24]; a1 = fma(s3, s3, a1);
                    if (dl == 0) { double s4 = ctd[4] - pc[32]; a0 = fma(s4, s4, a0); }
                }
                double acc = a0 + a1;
                acc += __shfl_down_sync(0xffffffffu, acc, 4);
                acc += __shfl_down_sync(0xffffffffu, acc, 2);
                acc += __shfl_down_sync(0xffffffffu, acc, 1);
                if (act && dl == 0) {
                    double cost = (S2t - s_s2[c]) - acc * s_recip[t - c];
                    val = s_Fc[c] + cost + PEN;
                }
            }
            double v0 = __shfl_sync(0xffffffffu, val, 0);
            double v1 = __shfl_sync(0xffffffffu, val, 8);
            double v2 = __shfl_sync(0xffffffffu, val, 16);
            double v3 = __shfl_sync(0xffffffffu, val, 24);
            double bv = v0; int bj = 0;
            if (v1 < bv) { bv = v1; bj = 1; }
            if (v2 < bv) { bv = v2; bj = 2; }
            if (v3 < bv) { bv = v3; bj = 3; }
            if (lane == 0) { s_Fc[t] = bv; s_prev[t] = s_cands[bj]; }
            double thr = bv + PEN;
            double vm = (lane == 0) ? v0 : (lane == 1) ? v1 : (lane == 2) ? v2 : v3;
            bool keep = (lane < ncand) && (vm <= thr);
            unsigned msk = __ballot_sync(0xffffffffu, keep);
            short cj = (lane < ncand) ? s_cands[lane] : (short)0;
            int pos = __popc(msk & ((1u << lane) - 1u));
            __syncwarp();
            if (keep) s_cands[pos] = cj;
            int newn = __popc(msk);
            if (lane == 0) s_cands[newn] = (short)t;
            ncand = newn + 1;
            __syncwarp();
        } else {
            // ---------- general smem path (R11) with dual accumulators -----
            for (int base = 0; base < ncand; base += 4) {
                int j = base + cg;
                double a0 = 0.0, a1 = 0.0;
                int c = 0;
                bool act2 = (j < ncand);
                if (act2) {
                    c = s_cands[j];
                    const double* pc = s_cs + c * 33;
                    double s0 = ctd[0] - pc[dl];      a0 = fma(s0, s0, a0);
                    double s1 = ctd[1] - pc[dl + 8];  a1 = fma(s1, s1, a1);
                    double s2 = ctd[2] - pc[dl + 16]; a0 = fma(s2, s2, a0);
                    double s3 = ctd[3] - pc[dl + 24]; a1 = fma(s3, s3, a1);
                    if (dl == 0) { double s4 = ctd[4] - pc[32]; a0 = fma(s4, s4, a0); }
                }
                double acc = a0 + a1;
                acc += __shfl_down_sync(0xffffffffu, acc, 4);
                acc += __shfl_down_sync(0xffffffffu, acc, 2);
                acc += __shfl_down_sync(0xffffffffu, acc, 1);
                if (act2 && dl == 0) {
                    double cost = (S2t - s_s2[c]) - acc * s_recip[t - c];
                    s_vals[j] = s_Fc[c] + cost + PEN;
                }
            }
            __syncwarp();

            double bv = 1e300; int bj = 1 << 30;
            for (int j = lane; j < ncand; j += 32) {
                double v = s_vals[j];
                if (v < bv) { bv = v; bj = j; }
            }
            #pragma unroll
            for (int o = 16; o; o >>= 1) {
                double ov = __shfl_down_sync(0xffffffffu, bv, o);
                int    oj = __shfl_down_sync(0xffffffffu, bj, o);
                if (ov < bv || (ov == bv && oj < bj)) { bv = ov; bj = oj; }
            }
            bv = __shfl_sync(0xffffffffu, bv, 0);
            bj = __shfl_sync(0xffffffffu, bj, 0);
            if (lane == 0) { s_Fc[t] = bv; s_prev[t] = s_cands[bj]; }
            __syncwarp();

            double thr = bv + PEN;
            int newn = 0;
            for (int base = 0; base < ncand; base += 32) {
                int j = base + lane;
                short cj = 0; bool keep = false;
                if (j < ncand) { cj = s_cands[j]; keep = (s_vals[j] <= thr); }
                unsigned msk = __ballot_sync(0xffffffffu, keep);
                int pos = newn + __popc(msk & ((1u << lane) - 1u));
                __syncwarp();
                if (keep) s_cands[pos] = cj;
                newn += __popc(msk);
                __syncwarp();
            }
            if (lane == 0) s_cands[newn] = (short)t;
            ncand = newn + 1;
            __syncwarp();
        }
    }

    if (lane == 0) {
        short bps[NF + 1];
        int nb = 0, t = NF;
        while (t > 0) { bps[nb++] = (short)t; t = s_prev[t]; }
        int bnd[MAXSEG];
        int bc = 1; bnd[0] = 0;
        for (int ii = nb - 1; ii >= 1; --ii) {
            int k = bps[ii];
            int bpos = (k < NF) ? HOP * k : Ln;
            if (bpos > Ln) bpos = Ln;
            if (bpos - bnd[bc - 1] >= 8 && bc < MAXSEG - 1) bnd[bc++] = bpos;
        }
        if (Ln - bnd[bc - 1] < 8 && bc > 1) bc--;
        bnd[bc++] = Ln;
        int nseg = bc - 1;
        int off = 0;
        for (int s = 0; s < nseg; ++s) {
            g_seg_s[b][s]   = bnd[s];
            g_seg_e[b][s]   = bnd[s + 1];
            g_seg_off[b][s] = off;
            off += (bnd[s + 1] - bnd[s]) >> 1;
        }
        g_nseg[b] = nseg;
    }
}

// ---- 5) fused: fp32 pairwise mean + DS-Goertzel + stats (warp/segment) -----
__global__ void k_segspec() {
    __shared__ float buf[4][SEGBUF];
    int b = blockIdx.y;
    int wid = threadIdx.x >> 5, lane = threadIdx.x & 31;
    int nseg = g_nseg[b];
    int wg = blockIdx.x * 4 + wid;
    int nwarp = gridDim.x * 4;
    float* wb = buf[wid];

    for (int seg = wg; seg < nseg; seg += nwarp) {
        int s = g_seg_s[b][seg], e = g_seg_e[b][seg];
        int n = e - s, nf = n >> 1;
        const float* sp = &g_sig[b][s];

        float mean = 0.0f;
        if (lane == 0) mean = __fdiv_rn(np_pairwise_sum(sp, n), (float)n);
        mean = __shfl_sync(0xffffffffu, mean, 0);

        bool small = (n <= SEGBUF);
        __syncwarp();
        if (small)
            for (int t = lane; t < n; t += 32) wb[t] = sp[t] - mean;
        __syncwarp();

        double pw[16];
        int nb = 0;
        double tot = 0.0, mv = -1.0; int mk = 1 << 30;

        for (int k = lane + 1; k <= nf; k += 32) {
            DS coeff;
            if (n == 32) { float2 cc = c_c32[k]; coeff = {cc.x, cc.y}; }
            else coeff = ds_from_d(2.0 * cos(2.0 * PI_D * (double)k / (double)n));

            DS s1 = {0.f, 0.f}, s2 = {0.f, 0.f};
            if (small) {
                for (int t = 0; t < n; ++t) {
                    DS t1 = ds_add({wb[t], 0.f}, ds_neg(s2));
                    DS sn = ds_add(t1, ds_mul(coeff, s1));
                    s2 = s1; s1 = sn;
                }
            } else {
                for (int t = 0; t < n; ++t) {
                    float v = sp[t] - mean;
                    DS t1 = ds_add({v, 0.f}, ds_neg(s2));
                    DS sn = ds_add(t1, ds_mul(coeff, s1));
                    s2 = s1; s1 = sn;
                }
            }
            DS aa = ds_mul(s1, s1);
            DS bb = ds_mul(s2, s2);
            DS cc = ds_mul(ds_mul(coeff, s1), s2);
            DS pp = ds_add(ds_add(aa, bb), ds_neg(cc));
            double pwv = (double)pp.hi + (double)pp.lo;
            if (pwv < 0.0) pwv = 0.0;
            if (small) pw[nb] = pwv;
            else g_spec[b][g_seg_off[b][seg] + (k - 1)] = pwv;
            ++nb;
            tot += pwv;
            if (pwv > mv) { mv = pwv; mk = k; }
        }
        __syncwarp();

        #pragma unroll
        for (int o = 16; o; o >>= 1) {
            tot += __shfl_down_sync(0xffffffffu, tot, o);
            double ov = __shfl_down_sync(0xffffffffu, mv, o);
            int    ok = __shfl_down_sync(0xffffffffu, mk, o);
            if (ov > mv || (ov == mv && ok < mk)) { mv = ov; mk = ok; }
        }
        tot = __shfl_sync(0xffffffffu, tot, 0);
        mk  = __shfl_sync(0xffffffffu, mk, 0);

        double dpv, bwvv;
        if (tot <= 0.0 || nf < 1) {
            dpv = (double)n; bwvv = 0.0;
        } else {
            double invtot = 1.0 / tot, invnf = 1.0 / (double)nf;
            double cacc = 0.0;
            { int i2 = 0;
              for (int k = lane + 1; k <= nf; k += 32) {
                  double v = small ? pw[i2++] : g_spec[b][g_seg_off[b][seg] + (k - 1)];
                  cacc += (v * invtot) * ((double)k * invnf);
              } }
            #pragma unroll
            for (int o = 16; o; o >>= 1) cacc += __shfl_down_sync(0xffffffffu, cacc, o);
            cacc = __shfl_sync(0xffffffffu, cacc, 0);

            double bacc = 0.0;
            { int i2 = 0;
              for (int k = lane + 1; k <= nf; k += 32) {
                  double v = small ? pw[i2++] : g_spec[b][g_seg_off[b][seg] + (k - 1)];
                  double fd = (double)k * invnf - cacc;
                  bacc += (v * invtot) * fd * fd;
              } }
            #pragma unroll
            for (int o = 16; o; o >>= 1) bacc += __shfl_down_sync(0xffffffffu, bacc, o);
            bacc = __shfl_sync(0xffffffffu, bacc, 0);

            dpv  = (double)n / (double)mk;
            bwvv = sqrt(bacc);
        }

        if (lane == 0) {
            g_dp[b][seg]  = dpv;
            g_bwv[b][seg] = bwvv;
            double raw = dpv / (1.0 + bwvv);
            double r = rint(raw * 0.5);
            int pl = (int)(2.0 * r);
            pl = pl < 8 ? 8 : (pl > 64 ? 64 : pl);
            g_pl[b][seg] = pl;
        }
        __syncwarp();
    }
}

// ------------------------- 6) token build (scan) ----------------------------
__global__ void k_tokens() {
    __shared__ int cnt[512];
    int b = blockIdx.x, tid = threadIdx.x;
    int nseg = g_nseg[b];
    int c = 0, s = 0, e = 0, pl = 8;
    if (tid < nseg) {
        s = g_seg_s[b][tid]; e = g_seg_e[b][tid]; pl = g_pl[b][tid];
        int len = e - s;
        int nfl = len / pl;
        c = nfl + ((len - nfl * pl) > 0 ? 1 : 0);
    }
    cnt[tid] = c;
    __syncthreads();
    for (int o = 1; o < 512; o <<= 1) {
        int v = cnt[tid];
        if (tid >= o) v += cnt[tid - o];
        __syncthreads();
        cnt[tid] = v;
        __syncthreads();
    }
    if (tid < nseg) {
        int off = cnt[tid] - c;
        int len = e - s;
        int nfl = len / pl;
        for (int i = 0; i < nfl; ++i) {
            g_tok_s[b][off + i]   = s + i * pl;
            g_tok_e[b][off + i]   = s + (i + 1) * pl;
            g_tok_seg[b][off + i] = tid;
        }
        if (nfl * pl < len) {
            g_tok_s[b][off + nfl]   = s + nfl * pl;
            g_tok_e[b][off + nfl]   = e;
            g_tok_seg[b][off + nfl] = tid;
        }
    }
    if (tid == 0) g_ntok[b] = cnt[511];
}

// -------------------------- 7a) scalar outputs ------------------------------
__global__ void k_scalars(float* __restrict__ o_mask, float* __restrict__ o_start,
                          float* __restrict__ o_end, float* __restrict__ o_center,
                          float* __restrict__ o_span, float* __restrict__ o_regime,
                          int mt) {
    int i = blockIdx.x * blockDim.x + threadIdx.x;
    int b = blockIdx.y;
    if (i >= mt) return;
    float m = 0.f, st = 0.f, en = 0.f, ce = 0.f, sp = 0.f, r0 = 0.f, r1 = 0.f, r2 = 0.f;
    if (i < g_ntok[b]) {
        int s = g_tok_s[b][i], e = g_tok_e[b][i], seg = g_tok_seg[b][i];
        m = 1.0f;
        st = (float)s; en = (float)e;
        ce = ((float)s + (float)e - 1.0f) * 0.5f / 16383.0f;
        sp = (float)(e - s) / 16384.0f;
        int sl = g_seg_e[b][seg] - g_seg_s[b][seg];
        r0 = (float)(g_dp[b][seg] / 16384.0);
        r1 = (float)g_bwv[b][seg];
        r2 = (float)((double)sl / 16384.0);
    }
    size_t idx = (size_t)b * mt + i;
    o_mask[idx] = m; o_start[idx] = st; o_end[idx] = en;
    o_center[idx] = ce; o_span[idx] = sp;
    o_regime[idx * 3 + 0] = r0;
    o_regime[idx * 3 + 1] = r1;
    o_regime[idx * 3 + 2] = r2;
}

__global__ void k_ntok(float* __restrict__ o_ntok) {
    int b = threadIdx.x;
    if (b < Bn) o_ntok[b] = (float)g_ntok[b];
}

// ---- 7b) patches (gather + lerp) g_x -> d_out, float4 stores ---------------
__global__ __launch_bounds__(256) void k_patches(float* __restrict__ o_patch, int mt) {
    int b = blockIdx.y;
    int tok = blockIdx.x * 2 + (threadIdx.x >> 7);
    int r = threadIdx.x & 127;
    int c = r >> 2, q = r & 3;
    if (tok >= mt) return;

    size_t obase = (((size_t)b * mt + tok) * Cn + c) * ANCH + q * 4;
    float4 v = make_float4(0.f, 0.f, 0.f, 0.f);
    if (tok < g_ntok[b]) {
        int s = g_tok_s[b][tok], e = g_tok_e[b][tok];
        int il = e - s;
        float scale = (float)il / 16.0f;
        const float* row = g_x[b][c] + s;
        float o[4];
        #pragma unroll
        for (int jj = 0; jj < 4; ++jj) {
            int j = q * 4 + jj;
            float coord = ((float)j + 0.5f) * scale - 0.5f;
            coord = fminf(fmaxf(coord, 0.0f), (float)(il - 1));
            int l = (int)floorf(coord);
            int h = min(l + 1, il - 1);
            float w = coord - (float)l;
            o[jj] = row[l] * (1.0f - w) + row[h] * w;
        }
        v = make_float4(o[0], o[1], o[2], o[3]);
    }
    *(float4*)(o_patch + obase) = v;
}

// --------------------------------- launch -----------------------------------
extern "C" void kernel_launch(void* const* d_in, const int* in_sizes, int n_in,
                              void* d_out, int out_size) {
    const float* x = (const float*)d_in[0];
    float* out = (float*)d_out;

    long long mt_ll = ((long long)out_size - Bn) / (16384 + 5 * Bn + 3 * Bn);
    if (mt_ll < 1) mt_ll = 1;
    int mt = (int)mt_ll;

    float* o_patch  = out;
    float* o_mask   = out + (size_t)Bn * mt * Cn * ANCH;
    float* o_start  = o_mask   + (size_t)Bn * mt;
    float* o_end    = o_start  + (size_t)Bn * mt;
    float* o_center = o_end    + (size_t)Bn * mt;
    float* o_span   = o_center + (size_t)Bn * mt;
    float* o_regime = o_span   + (size_t)Bn * mt;
    float* o_ntok   = o_regime + (size_t)Bn * mt * 3;

    static bool attr_done = false;
    if (!attr_done) {
        cudaFuncSetAttribute(k_pelt, cudaFuncAttributeMaxDynamicSharedMemorySize,
                             (int)PELT_SMEM);
        attr_done = true;
    }

    k_init<<<1, 512>>>();
    k_sig<<<dim3(16, Bn), 256>>>(x);
    k_feats<<<dim3(NF, Bn), WIN>>>();
    k_prefix<<<dim3(ND, Bn), 32>>>();
    k_s2<<<Bn, NF + 1>>>();
    k_pelt<<<Bn, 256, PELT_SMEM>>>();
    k_segspec<<<dim3(128, Bn), 128>>>();
    k_tokens<<<Bn, 512>>>();
    k_scalars<<<dim3((mt + 255) / 256, Bn), 256>>>(o_mask, o_start, o_end,
                                                   o_center, o_span, o_regime, mt);
    k_ntok<<<1, Bn>>>(o_ntok);
    k_patches<<<dim3((mt + 1) / 2, Bn), 256>>>(o_patch, mt);
}

// round 15
// speedup vs baseline: 1.3993x; 1.0568x over previous
#include <cuda_runtime.h>
#include <math.h>

namespace {
constexpr int    Bn = 32, Cn = 32, Ln = 16384, WIN = 64, HOP = 32;
constexpr int    NF = 511, ND = 33;
constexpr double PEN = 5.0;
constexpr int    MAXSEG = 520, MAXTOK = 4608, ANCH = 16;
constexpr double PI_D = 3.14159265358979323846264338327950288;
constexpr int    SEGBUF = 1024;
constexpr int    PELT_DBL  = 16896 + 512 + 512 + 512 + 512;
constexpr size_t PELT_SMEM = PELT_DBL * 8 + (512 + 514) * 2 + 16;
}

// ------------------------------- scratch ----------------------------------
__device__ float  g_x[Bn][Cn][Ln];
__device__ float  g_sig[Bn][Ln];
__device__ double g_feats[Bn][NF][ND];
__device__ double g_cs [Bn][NF + 1][ND];
__device__ double g_cs2[Bn][NF + 1][ND];
__device__ double g_s2 [Bn][NF + 1];
__device__ int    g_nseg[Bn];
__device__ int    g_seg_s[Bn][MAXSEG];
__device__ int    g_seg_e[Bn][MAXSEG];
__device__ int    g_seg_off[Bn][MAXSEG];
__device__ double g_spec[Bn][Ln / 2 + 8];
__device__ double g_dp[Bn][MAXSEG];
__device__ double g_bwv[Bn][MAXSEG];
__device__ int    g_pl[Bn][MAXSEG];
__device__ int    g_ntok[Bn];
__device__ int    g_tok_s[Bn][MAXTOK];
__device__ int    g_tok_e[Bn][MAXTOK];
__device__ int    g_tok_seg[Bn][MAXTOK];

// precomputed constants
__device__ float2 c_tw_re[WIN], c_tw_im[WIN], c_win[WIN];
__device__ float2 c_c32[17];
__device__ float2 c_lnc[11];
__device__ float2 c_ln2;
__device__ float2 c_eps;
__device__ double c_recip[NF + 1];

// ---------------------------- double-single ops ----------------------------
struct DS { float hi, lo; };
__device__ __forceinline__ DS two_sum(float a, float b) {
    float s = a + b, bb = s - a;
    float e = (a - (s - bb)) + (b - bb);
    return {s, e};
}
__device__ __forceinline__ DS quick2(float a, float b) {
    float s = a + b;
    return {s, b - (s - a)};
}
__device__ __forceinline__ DS ds_add(DS a, DS b) {
    DS s = two_sum(a.hi, b.hi);
    return quick2(s.hi, s.lo + a.lo + b.lo);
}
__device__ __forceinline__ DS ds_mul(DS a, DS b) {
    float p = a.hi * b.hi;
    float e = fmaf(a.hi, b.hi, -p);
    e = fmaf(a.hi, b.lo, e);
    e = fmaf(a.lo, b.hi, e);
    return quick2(p, e);
}
__device__ __forceinline__ DS ds_neg(DS a) { return {-a.hi, -a.lo}; }
__device__ __forceinline__ DS ds_from_d(double v) {
    float hi = (float)v;
    return {hi, (float)(v - (double)hi)};
}

// DS natural log; v > 0 well inside float range. abs err ~1e-13.
__device__ DS ds_log(DS v) {
    int e;
    float mh = frexpf(v.hi, &e);
    if (mh < 0.7071067811865476f) e -= 1;
    float sc = ldexpf(1.0f, -e);
    DS m = {v.hi * sc, v.lo * sc};
    DS num = ds_add(m, {-1.0f, 0.0f});
    DS den = ds_add(m, { 1.0f, 0.0f});
    float r = 1.0f / den.hi;
    float q1 = num.hi * r;
    DS t  = ds_add(num, ds_neg(ds_mul(den, {q1, 0.f})));
    float q2 = t.hi * r;
    DS t2 = ds_add(t,  ds_neg(ds_mul(den, {q2, 0.f})));
    float q3 = t2.hi * r;
    DS z = ds_add(ds_add({q1, 0.f}, {q2, 0.f}), {q3, 0.f});
    DS w = ds_mul(z, z);
    DS p = {c_lnc[10].x, c_lnc[10].y};
    #pragma unroll
    for (int k = 9; k >= 0; --k)
        p = ds_add(ds_mul(p, w), {c_lnc[k].x, c_lnc[k].y});
    DS lnm = ds_mul(ds_mul({2.0f, 0.f}, z), p);
    return ds_add(ds_mul({(float)e, 0.f}, {c_ln2.x, c_ln2.y}), lnm);
}

// numpy pairwise sum (float32), exact replication
__device__ float np_pairwise_sum(const float* a, int n) {
    if (n < 8) {
        float r = 0.0f;
        for (int i = 0; i < n; ++i) r += a[i];
        return r;
    } else if (n <= 128) {
        float r[8];
        #pragma unroll
        for (int j = 0; j < 8; ++j) r[j] = a[j];
        int i = 8;
        for (; i < n - (n % 8); i += 8) {
            #pragma unroll
            for (int j = 0; j < 8; ++j) r[j] += a[i + j];
        }
        float res = ((r[0] + r[1]) + (r[2] + r[3])) + ((r[4] + r[5]) + (r[6] + r[7]));
        for (; i < n; ++i) res += a[i];
        return res;
    } else {
        int n2 = n / 2;
        n2 -= n2 % 8;
        return np_pairwise_sum(a, n2) + np_pairwise_sum(a + n2, n - n2);
    }
}

// ------------------------------ 0) init ------------------------------------
__global__ void k_init() {
    int i = threadIdx.x;
    if (i < WIN) {
        double ang = -2.0 * PI_D * (double)i / 64.0;
        double sn, co;
        sincos(ang, &sn, &co);
        DS a = ds_from_d(co), b = ds_from_d(sn);
        c_tw_re[i] = make_float2(a.hi, a.lo);
        c_tw_im[i] = make_float2(b.hi, b.lo);
        DS wd = ds_from_d(0.5 - 0.5 * cos(2.0 * PI_D * (double)i / 63.0));
        c_win[i] = make_float2(wd.hi, wd.lo);
    }
    if (i <= 16) {
        DS c = ds_from_d(2.0 * cos(2.0 * PI_D * (double)i / 32.0));
        c_c32[i] = make_float2(c.hi, c.lo);
    }
    if (i <= 10) {
        DS c = ds_from_d(1.0 / (double)(2 * i + 1));
        c_lnc[i] = make_float2(c.hi, c.lo);
    }
    if (i == 0) {
        DS l2 = ds_from_d(0.69314718055994530941723212145818);
        c_ln2 = make_float2(l2.hi, l2.lo);
        DS ep = ds_from_d(1e-8);
        c_eps = make_float2(ep.hi, ep.lo);
    }
    if (i <= NF) c_recip[i] = i ? 1.0 / (double)i : 0.0;
}

// -------- 1) stage x -> g_x (HBM) + channel mean (float4 streaming) ---------
__global__ void k_sig(const float* __restrict__ x) {
    int t4 = blockIdx.x * blockDim.x + threadIdx.x;
    int b = blockIdx.y;
    if (t4 >= Ln / 4) return;
    const float4* p = (const float4*)(x + (size_t)b * Cn * Ln) + t4;
    float4 s = make_float4(0.f, 0.f, 0.f, 0.f);
    #pragma unroll
    for (int c = 0; c < Cn; ++c) {
        float4 v = p[(size_t)c * (Ln / 4)];
        ((float4*)g_x[b][c])[t4] = v;
        s.x += v.x; s.y += v.y; s.z += v.z; s.w += v.w;
    }
    s.x *= 0.03125f; s.y *= 0.03125f; s.z *= 0.03125f; s.w *= 0.03125f;
    ((float4*)g_sig[b])[t4] = s;
}

// ------------- 2) spectrogram features (DS fp32 DFT + DS log) --------------
__global__ void k_feats() {
    __shared__ float2 sv[WIN];
    __shared__ float2 twr[WIN], twi[WIN];
    __shared__ float  fr[WIN];
    __shared__ float  smean;
    int b = blockIdx.y, f = blockIdx.x, i = threadIdx.x;

    twr[i] = c_tw_re[i]; twi[i] = c_tw_im[i];
    fr[i] = g_sig[b][f * HOP + i];
    __syncthreads();

    if (i == 0) {
        float r[8];
        #pragma unroll
        for (int j = 0; j < 8; ++j) r[j] = fr[j];
        for (int o = 8; o < 64; o += 8) {
            #pragma unroll
            for (int j = 0; j < 8; ++j) r[j] += fr[o + j];
        }
        float s = ((r[0] + r[1]) + (r[2] + r[3])) + ((r[4] + r[5]) + (r[6] + r[7]));
        smean = s / 64.0f;
    }
    __syncthreads();

    {
        float d = fr[i] - smean;
        float2 w = c_win[i];
        float p = d * w.x;
        float e = fmaf(d, w.x, -p);
        e = fmaf(d, w.y, e);
        DS r = quick2(p, e);
        sv[i] = make_float2(r.hi, r.lo);
    }
    __syncthreads();

    if (i < ND) {
        DS re = {0.f, 0.f}, im = {0.f, 0.f};
        #pragma unroll 4
        for (int t = 0; t < WIN; ++t) {
            int m = (i * t) & 63;
            DS v  = {sv[t].x, sv[t].y};
            DS cr = {twr[m].x, twr[m].y};
            DS ci = {twi[m].x, twi[m].y};
            re = ds_add(re, ds_mul(v, cr));
            im = ds_add(im, ds_mul(v, ci));
        }
        DS p2 = ds_add(ds_mul(re, re), ds_mul(im, im));
        p2 = ds_add(p2, {c_eps.x, c_eps.y});
        DS lg = ds_log(p2);
        g_feats[b][f][i] = (double)lg.hi + (double)lg.lo;
    }
}

// -------- 3a) prefix sums: warp-per-(d,b) Kogge-Stone scan with carry -------
__global__ void k_prefix() {
    int d = blockIdx.x, b = blockIdx.y, lane = threadIdx.x;
    double carry = 0.0, carry2 = 0.0;
    if (lane == 0) { g_cs[b][0][d] = 0.0; g_cs2[b][0][d] = 0.0; }
    for (int base = 0; base < NF; base += 32) {
        int t = base + lane;
        double v  = (t < NF) ? g_feats[b][t][d] : 0.0;
        double v2 = v * v;
        #pragma unroll
        for (int o = 1; o < 32; o <<= 1) {
            double n1 = __shfl_up_sync(0xffffffffu, v,  o);
            double n2 = __shfl_up_sync(0xffffffffu, v2, o);
            if (lane >= o) { v += n1; v2 += n2; }
        }
        v += carry; v2 += carry2;
        if (t < NF) {
            g_cs[b][t + 1][d]  = v;
            g_cs2[b][t + 1][d] = v2;
        }
        carry  = __shfl_sync(0xffffffffu, v, 31);
        carry2 = __shfl_sync(0xffffffffu, v2, 31);
    }
}

// -------- 3b) S2 totals: sum over d of cs2 ----------------------------------
__global__ void k_s2() {
    int b = blockIdx.x, t = threadIdx.x;
    double s = 0.0;
    #pragma unroll
    for (int dd = 0; dd < ND; ++dd) s += g_cs2[b][t][dd];
    g_s2[b][t] = s;
}

// ------ 4) PELT DP: R11 structure byte-identical; launch_bounds + d2 stage --
__global__ __launch_bounds__(256, 1) void k_pelt() {
    extern __shared__ double dyn[];
    double* s_cs    = dyn;                 // 16896 = 512*33
    double* s_s2    = dyn + 16896;         // 512
    double* s_Fc    = dyn + 17408;         // 512
    double* s_vals  = dyn + 17920;         // 512
    double* s_recip = dyn + 18432;         // 512
    short*  s_prev  = (short*)(dyn + 18944);        // 512 shorts
    short*  s_cands = s_prev + 512;                 // 514 shorts

    int b = blockIdx.x, tid = threadIdx.x;

    // stage cs via double2 (8448 vector loads), s2/recip scalar
    const double2* gc2 = (const double2*)g_cs[b];
    double2* sc2 = (double2*)s_cs;
    for (int i = tid; i < 8448; i += 256) sc2[i] = gc2[i];
    for (int i = tid; i < 512;  i += 256) {
        s_s2[i]    = g_s2[b][i];
        s_recip[i] = c_recip[i];
    }
    __syncthreads();
    if (tid >= 32) return;

    int lane = tid;
    int cg = lane >> 3;   // candidate slot within pass (0..3)
    int dl = lane & 7;    // dim lane (0..7)
    if (lane == 0) { s_Fc[0] = -PEN; s_cands[0] = 0; }
    int ncand = 1;
    __syncwarp();

    for (int t = 1; t <= NF; ++t) {
        const double* ct = s_cs + t * 33;
        double S2t = s_s2[t];
        double ctd[5];
        #pragma unroll
        for (int q = 0; q < 5; ++q) {
            int d = dl + q * 8;
            ctd[q] = (d < ND) ? ct[d] : 0.0;
        }

        if (ncand <= 4) {
            // ---------- register fast path (R11, untouched) ----------
            int j = cg;
            double val = 1e300;
            int c = 0;
            bool act = (j < ncand);
            if (act) c = s_cands[j];
            {
                const double* pc = s_cs + c * 33;
                double acc = 0.0;
                if (act) {
                    #pragma unroll
                    for (int q = 0; q < 5; ++q) {
                        int d = dl + q * 8;
                        if (d < ND) {
                            double su = ctd[q] - pc[d];
                            acc = fma(su, su, acc);
                        }
                    }
                }
                acc += __shfl_down_sync(0xffffffffu, acc, 4);
                acc += __shfl_down_sync(0xffffffffu, acc, 2);
                acc += __shfl_down_sync(0xffffffffu, acc, 1);
                if (act && dl == 0) {
                    double cost = (S2t - s_s2[c]) - acc * s_recip[t - c];
                    val = s_Fc[c] + cost + PEN;
                }
            }
            double v0 = __shfl_sync(0xffffffffu, val, 0);
            double v1 = __shfl_sync(0xffffffffu, val, 8);
            double v2 = __shfl_sync(0xffffffffu, val, 16);
            double v3 = __shfl_sync(0xffffffffu, val, 24);
            double bv = v0; int bj = 0;
            if (v1 < bv) { bv = v1; bj = 1; }
            if (v2 < bv) { bv = v2; bj = 2; }
            if (v3 < bv) { bv = v3; bj = 3; }
            if (lane == 0) { s_Fc[t] = bv; s_prev[t] = s_cands[bj]; }
            double thr = bv + PEN;
            double vm = (lane == 0) ? v0 : (lane == 1) ? v1 : (lane == 2) ? v2 : v3;
            bool keep = (lane < ncand) && (vm <= thr);
            unsigned msk = __ballot_sync(0xffffffffu, keep);
            short cj = (lane < ncand) ? s_cands[lane] : (short)0;
            int pos = __popc(msk & ((1u << lane) - 1u));
            __syncwarp();
            if (keep) s_cands[pos] = cj;
            int newn = __popc(msk);
            if (lane == 0) s_cands[newn] = (short)t;
            ncand = newn + 1;
            __syncwarp();
        } else {
            // ---------- general smem path (R11, untouched) ----------
            for (int base = 0; base < ncand; base += 4) {
                int j = base + cg;
                double acc = 0.0;
                int c = 0;
                bool act = (j < ncand);
                if (act) {
                    c = s_cands[j];
                    const double* pc = s_cs + c * 33;
                    #pragma unroll
                    for (int q = 0; q < 5; ++q) {
                        int d = dl + q * 8;
                        if (d < ND) {
                            double su = ctd[q] - pc[d];
                            acc = fma(su, su, acc);
                        }
                    }
                }
                acc += __shfl_down_sync(0xffffffffu, acc, 4);
                acc += __shfl_down_sync(0xffffffffu, acc, 2);
                acc += __shfl_down_sync(0xffffffffu, acc, 1);
                if (act && dl == 0) {
                    double cost = (S2t - s_s2[c]) - acc * s_recip[t - c];
                    s_vals[j] = s_Fc[c] + cost + PEN;
                }
            }
            __syncwarp();

            double bv = 1e300; int bj = 1 << 30;
            for (int j = lane; j < ncand; j += 32) {
                double v = s_vals[j];
                if (v < bv) { bv = v; bj = j; }
            }
            #pragma unroll
            for (int o = 16; o; o >>= 1) {
                double ov = __shfl_down_sync(0xffffffffu, bv, o);
                int    oj = __shfl_down_sync(0xffffffffu, bj, o);
                if (ov < bv || (ov == bv && oj < bj)) { bv = ov; bj = oj; }
            }
            bv = __shfl_sync(0xffffffffu, bv, 0);
            bj = __shfl_sync(0xffffffffu, bj, 0);
            if (lane == 0) { s_Fc[t] = bv; s_prev[t] = s_cands[bj]; }
            __syncwarp();

            double thr = bv + PEN;
            int newn = 0;
            for (int base = 0; base < ncand; base += 32) {
                int j = base + lane;
                short cj = 0; bool keep = false;
                if (j < ncand) { cj = s_cands[j]; keep = (s_vals[j] <= thr); }
                unsigned msk = __ballot_sync(0xffffffffu, keep);
                int pos = newn + __popc(msk & ((1u << lane) - 1u));
                __syncwarp();
                if (keep) s_cands[pos] = cj;
                newn += __popc(msk);
                __syncwarp();
            }
            if (lane == 0) s_cands[newn] = (short)t;
            ncand = newn + 1;
            __syncwarp();
        }
    }

    if (lane == 0) {
        short bps[NF + 1];
        int nb = 0, t = NF;
        while (t > 0) { bps[nb++] = (short)t; t = s_prev[t]; }
        int bnd[MAXSEG];
        int bc = 1; bnd[0] = 0;
        for (int ii = nb - 1; ii >= 1; --ii) {
            int k = bps[ii];
            int bpos = (k < NF) ? HOP * k : Ln;
            if (bpos > Ln) bpos = Ln;
            if (bpos - bnd[bc - 1] >= 8 && bc < MAXSEG - 1) bnd[bc++] = bpos;
        }
        if (Ln - bnd[bc - 1] < 8 && bc > 1) bc--;
        bnd[bc++] = Ln;
        int nseg = bc - 1;
        int off = 0;
        for (int s = 0; s < nseg; ++s) {
            g_seg_s[b][s]   = bnd[s];
            g_seg_e[b][s]   = bnd[s + 1];
            g_seg_off[b][s] = off;
            off += (bnd[s + 1] - bnd[s]) >> 1;
        }
        g_nseg[b] = nseg;
    }
}

// ---- 5) fused: fp32 pairwise mean + DS-Goertzel + stats (warp/segment) -----
__global__ void k_segspec() {
    __shared__ float buf[4][SEGBUF];
    int b = blockIdx.y;
    int wid = threadIdx.x >> 5, lane = threadIdx.x & 31;
    int nseg = g_nseg[b];
    int wg = blockIdx.x * 4 + wid;
    int nwarp = gridDim.x * 4;
    float* wb = buf[wid];

    for (int seg = wg; seg < nseg; seg += nwarp) {
        int s = g_seg_s[b][seg], e = g_seg_e[b][seg];
        int n = e - s, nf = n >> 1;
        const float* sp = &g_sig[b][s];

        float mean = 0.0f;
        if (lane == 0) mean = __fdiv_rn(np_pairwise_sum(sp, n), (float)n);
        mean = __shfl_sync(0xffffffffu, mean, 0);

        bool small = (n <= SEGBUF);
        __syncwarp();
        if (small)
            for (int t = lane; t < n; t += 32) wb[t] = sp[t] - mean;
        __syncwarp();

        double pw[16];
        int nb = 0;
        double tot = 0.0, mv = -1.0; int mk = 1 << 30;

        for (int k = lane + 1; k <= nf; k += 32) {
            DS coeff;
            if (n == 32) { float2 cc = c_c32[k]; coeff = {cc.x, cc.y}; }
            else coeff = ds_from_d(2.0 * cos(2.0 * PI_D * (double)k / (double)n));

            DS s1 = {0.f, 0.f}, s2 = {0.f, 0.f};
            if (small) {
                for (int t = 0; t < n; ++t) {
                    DS t1 = ds_add({wb[t], 0.f}, ds_neg(s2));
                    DS sn = ds_add(t1, ds_mul(coeff, s1));
                    s2 = s1; s1 = sn;
                }
            } else {
                for (int t = 0; t < n; ++t) {
                    float v = sp[t] - mean;
                    DS t1 = ds_add({v, 0.f}, ds_neg(s2));
                    DS sn = ds_add(t1, ds_mul(coeff, s1));
                    s2 = s1; s1 = sn;
                }
            }
            DS aa = ds_mul(s1, s1);
            DS bb = ds_mul(s2, s2);
            DS cc = ds_mul(ds_mul(coeff, s1), s2);
            DS pp = ds_add(ds_add(aa, bb), ds_neg(cc));
            double pwv = (double)pp.hi + (double)pp.lo;
            if (pwv < 0.0) pwv = 0.0;
            if (small) pw[nb] = pwv;
            else g_spec[b][g_seg_off[b][seg] + (k - 1)] = pwv;
            ++nb;
            tot += pwv;
            if (pwv > mv) { mv = pwv; mk = k; }
        }
        __syncwarp();

        #pragma unroll
        for (int o = 16; o; o >>= 1) {
            tot += __shfl_down_sync(0xffffffffu, tot, o);
            double ov = __shfl_down_sync(0xffffffffu, mv, o);
            int    ok = __shfl_down_sync(0xffffffffu, mk, o);
            if (ov > mv || (ov == mv && ok < mk)) { mv = ov; mk = ok; }
        }
        tot = __shfl_sync(0xffffffffu, tot, 0);
        mk  = __shfl_sync(0xffffffffu, mk, 0);

        double dpv, bwvv;
        if (tot <= 0.0 || nf < 1) {
            dpv = (double)n; bwvv = 0.0;
        } else {
            double invtot = 1.0 / tot, invnf = 1.0 / (double)nf;
            double cacc = 0.0;
            { int i2 = 0;
              for (int k = lane + 1; k <= nf; k += 32) {
                  double v = small ? pw[i2++] : g_spec[b][g_seg_off[b][seg] + (k - 1)];
                  cacc += (v * invtot) * ((double)k * invnf);
              } }
            #pragma unroll
            for (int o = 16; o; o >>= 1) cacc += __shfl_down_sync(0xffffffffu, cacc, o);
            cacc = __shfl_sync(0xffffffffu, cacc, 0);

            double bacc = 0.0;
            { int i2 = 0;
              for (int k = lane + 1; k <= nf; k += 32) {
                  double v = small ? pw[i2++] : g_spec[b][g_seg_off[b][seg] + (k - 1)];
                  double fd = (double)k * invnf - cacc;
                  bacc += (v * invtot) * fd * fd;
              } }
            #pragma unroll
            for (int o = 16; o; o >>= 1) bacc += __shfl_down_sync(0xffffffffu, bacc, o);
            bacc = __shfl_sync(0xffffffffu, bacc, 0);

            dpv  = (double)n / (double)mk;
            bwvv = sqrt(bacc);
        }

        if (lane == 0) {
            g_dp[b][seg]  = dpv;
            g_bwv[b][seg] = bwvv;
            double raw = dpv / (1.0 + bwvv);
            double r = rint(raw * 0.5);
            int pl = (int)(2.0 * r);
            pl = pl < 8 ? 8 : (pl > 64 ? 64 : pl);
            g_pl[b][seg] = pl;
        }
        __syncwarp();
    }
}

// --------------- 6) token build (scan) + ntok output -----------------------
__global__ void k_tokens(float* __restrict__ o_ntok) {
    __shared__ int cnt[512];
    int b = blockIdx.x, tid = threadIdx.x;
    int nseg = g_nseg[b];
    int c = 0, s = 0, e = 0, pl = 8;
    if (tid < nseg) {
        s = g_seg_s[b][tid]; e = g_seg_e[b][tid]; pl = g_pl[b][tid];
        int len = e - s;
        int nfl = len / pl;
        c = nfl + ((len - nfl * pl) > 0 ? 1 : 0);
    }
    cnt[tid] = c;
    __syncthreads();
    for (int o = 1; o < 512; o <<= 1) {
        int v = cnt[tid];
        if (tid >= o) v += cnt[tid - o];
        __syncthreads();
        cnt[tid] = v;
        __syncthreads();
    }
    if (tid < nseg) {
        int off = cnt[tid] - c;
        int len = e - s;
        int nfl = len / pl;
        for (int i = 0; i < nfl; ++i) {
            g_tok_s[b][off + i]   = s + i * pl;
            g_tok_e[b][off + i]   = s + (i + 1) * pl;
            g_tok_seg[b][off + i] = tid;
        }
        if (nfl * pl < len) {
            g_tok_s[b][off + nfl]   = s + nfl * pl;
            g_tok_e[b][off + nfl]   = e;
            g_tok_seg[b][off + nfl] = tid;
        }
    }
    if (tid == 0) {
        g_ntok[b] = cnt[511];
        o_ntok[b] = (float)cnt[511];
    }
}

// -------------------------- 7a) scalar outputs ------------------------------
__global__ void k_scalars(float* __restrict__ o_mask, float* __restrict__ o_start,
                          float* __restrict__ o_end, float* __restrict__ o_center,
                          float* __restrict__ o_span, float* __restrict__ o_regime,
                          int mt) {
    int i = blockIdx.x * blockDim.x + threadIdx.x;
    int b = blockIdx.y;
    if (i >= mt) return;
    float m = 0.f, st = 0.f, en = 0.f, ce = 0.f, sp = 0.f, r0 = 0.f, r1 = 0.f, r2 = 0.f;
    if (i < g_ntok[b]) {
        int s = g_tok_s[b][i], e = g_tok_e[b][i], seg = g_tok_seg[b][i];
        m = 1.0f;
        st = (float)s; en = (float)e;
        ce = ((float)s + (float)e - 1.0f) * 0.5f / 16383.0f;
        sp = (float)(e - s) / 16384.0f;
        int sl = g_seg_e[b][seg] - g_seg_s[b][seg];
        r0 = (float)(g_dp[b][seg] / 16384.0);
        r1 = (float)g_bwv[b][seg];
        r2 = (float)((double)sl / 16384.0);
    }
    size_t idx = (size_t)b * mt + i;
    o_mask[idx] = m; o_start[idx] = st; o_end[idx] = en;
    o_center[idx] = ce; o_span[idx] = sp;
    o_regime[idx * 3 + 0] = r0;
    o_regime[idx * 3 + 1] = r1;
    o_regime[idx * 3 + 2] = r2;
}

// ---- 7b) patches (gather + lerp) g_x -> d_out, float4 stores ---------------
__global__ __launch_bounds__(256) void k_patches(float* __restrict__ o_patch, int mt) {
    int b = blockIdx.y;
    int tok = blockIdx.x * 2 + (threadIdx.x >> 7);
    int r = threadIdx.x & 127;
    int c = r >> 2, q = r & 3;
    if (tok >= mt) return;

    size_t obase = (((size_t)b * mt + tok) * Cn + c) * ANCH + q * 4;
    float4 v = make_float4(0.f, 0.f, 0.f, 0.f);
    if (tok < g_ntok[b]) {
        int s = g_tok_s[b][tok], e = g_tok_e[b][tok];
        int il = e - s;
        float scale = (float)il / 16.0f;
        const float* row = g_x[b][c] + s;
        float o[4];
        #pragma unroll
        for (int jj = 0; jj < 4; ++jj) {
            int j = q * 4 + jj;
            float coord = ((float)j + 0.5f) * scale - 0.5f;
            coord = fminf(fmaxf(coord, 0.0f), (float)(il - 1));
            int l = (int)floorf(coord);
            int h = min(l + 1, il - 1);
            float w = coord - (float)l;
            o[jj] = row[l] * (1.0f - w) + row[h] * w;
        }
        v = make_float4(o[0], o[1], o[2], o[3]);
    }
    *(float4*)(o_patch + obase) = v;
}

// --------------------------------- launch -----------------------------------
extern "C" void kernel_launch(void* const* d_in, const int* in_sizes, int n_in,
                              void* d_out, int out_size) {
    const float* x = (const float*)d_in[0];
    float* out = (float*)d_out;

    long long mt_ll = ((long long)out_size - Bn) / (16384 + 5 * Bn + 3 * Bn);
    if (mt_ll < 1) mt_ll = 1;
    int mt = (int)mt_ll;

    float* o_patch  = out;
    float* o_mask   = out + (size_t)Bn * mt * Cn * ANCH;
    float* o_start  = o_mask   + (size_t)Bn * mt;
    float* o_end    = o_start  + (size_t)Bn * mt;
    float* o_center = o_end    + (size_t)Bn * mt;
    float* o_span   = o_center + (size_t)Bn * mt;
    float* o_regime = o_span   + (size_t)Bn * mt;
    float* o_ntok   = o_regime + (size_t)Bn * mt * 3;

    static bool attr_done = false;
    if (!attr_done) {
        cudaFuncSetAttribute(k_pelt, cudaFuncAttributeMaxDynamicSharedMemorySize,
                             (int)PELT_SMEM);
        attr_done = true;
    }

    k_init<<<1, 512>>>();
    k_sig<<<dim3(16, Bn), 256>>>(x);
    k_feats<<<dim3(NF, Bn), WIN>>>();
    k_prefix<<<dim3(ND, Bn), 32>>>();
    k_s2<<<Bn, NF + 1>>>();
    k_pelt<<<Bn, 256, PELT_SMEM>>>();
    k_segspec<<<dim3(128, Bn), 128>>>();
    k_tokens<<<Bn, 512>>>(o_ntok);
    k_scalars<<<dim3((mt + 255) / 256, Bn), 256>>>(o_mask, o_start, o_end,
                                                   o_center, o_span, o_regime, mt);
    k_patches<<<dim3((mt + 1) / 2, Bn), 256>>>(o_patch, mt);
}